// round 1
// baseline (speedup 1.0000x reference)
#include <cuda_runtime.h>
#include <math.h>

// ---------------------------------------------------------------------------
// CapsNet forward, B=512.
// Pipeline:
//   k_conv1   : x[512,3,28,28] -> h1[512,256,20,20]  (9x9 s1 + bias + relu)
//   k_conv2   : h1 -> h2[512,256,6,6] (+bias)        (9x9 s2)
//   k_squash_pc: h2 flat capsules (8 consecutive floats) -> u
//   k_uhat    : u_hat[b,cap,o,e] = sum_d u[b,cap,d]*W[cap,o,d,e]
//   routing (3 iters, b_logits never materialized; logits = uhat . vsum):
//     reduce_s(uniform) -> squash -> vsum=v0
//     logits(vsum) -> softmax c -> reduce_s(c) -> squash -> vsum+=v1
//     logits(vsum) -> softmax c -> reduce_s(c) -> squash -> d_out
// ---------------------------------------------------------------------------

// scratch (device globals: allowed; no runtime allocation)
__device__ float g_h1[512u * 256u * 400u];        // 209.7 MB
__device__ float g_h2[512u * 9216u];              // 18.9 MB
__device__ float g_u [512u * 9216u];              // 18.9 MB
__device__ float g_uhat[512u * 1152u * 160u];     // 377.5 MB
__device__ float g_c [512u * 1152u * 10u];        // 23.6 MB
__device__ float g_s [512u * 160u];
__device__ float g_vsum[512u * 160u];

// ---------------------------------------------------------------------------
// conv1 + relu: grid (512, 8), block 256.
// Block: one image, 32 output channels. Thread tile: 8 channels x 4 positions.
// ---------------------------------------------------------------------------
__global__ __launch_bounds__(256) void k_conv1(const float* __restrict__ x,
                                               const float* __restrict__ w1,
                                               const float* __restrict__ b1)
{
    __shared__ float xs[2352];      // 3*28*28
    __shared__ float ws[7776];      // 32 ch * 243, flat [co_local][243]
    const int b  = blockIdx.x;
    const int cg = blockIdx.y;      // 0..7 (channel group of 32)
    const int id = threadIdx.x;

    {
        const float4* xg = (const float4*)(x + b * 2352);
        float4* xs4 = (float4*)xs;
        for (int i = id; i < 588; i += 256) xs4[i] = xg[i];
        const float4* wg = (const float4*)(w1 + cg * 7776);
        float4* ws4 = (float4*)ws;
        for (int i = id; i < 1944; i += 256) ws4[i] = wg[i];
    }
    __syncthreads();

    const int ty = id & 3;          // channel row: co = cg*32 + ty + 4*i
    const int tx = id >> 2;         // 0..63: quad-position slot
    float bias[8];
#pragma unroll
    for (int i = 0; i < 8; i++) bias[i] = b1[cg * 32 + ty + 4 * i];

    for (int qi = 0; qi < 2; qi++) {
        int gq = tx + 64 * qi;      // 100 quads total (20 rows x 5 quad-cols)
        if (gq < 100) {
            int oy  = gq / 5;
            int oxb = (gq % 5) * 4;
            float acc[8][4];
#pragma unroll
            for (int i = 0; i < 8; i++)
#pragma unroll
                for (int j = 0; j < 4; j++) acc[i][j] = 0.f;

            for (int c = 0; c < 3; c++) {
                for (int ky = 0; ky < 9; ky++) {
                    const float* xrow = &xs[(c * 28 + oy + ky) * 28 + oxb];
                    float rin[12];
                    *(float4*)(rin)     = *(const float4*)(xrow);
                    *(float4*)(rin + 4) = *(const float4*)(xrow + 4);
                    *(float4*)(rin + 8) = *(const float4*)(xrow + 8);
                    const int kb = c * 81 + ky * 9;
#pragma unroll
                    for (int kx = 0; kx < 9; kx++) {
#pragma unroll
                        for (int i = 0; i < 8; i++) {
                            float w = ws[(ty + 4 * i) * 243 + kb + kx];
                            acc[i][0] = fmaf(w, rin[kx],     acc[i][0]);
                            acc[i][1] = fmaf(w, rin[kx + 1], acc[i][1]);
                            acc[i][2] = fmaf(w, rin[kx + 2], acc[i][2]);
                            acc[i][3] = fmaf(w, rin[kx + 3], acc[i][3]);
                        }
                    }
                }
            }
#pragma unroll
            for (int i = 0; i < 8; i++) {
                int co = cg * 32 + ty + 4 * i;
                float4 v;
                v.x = fmaxf(acc[i][0] + bias[i], 0.f);
                v.y = fmaxf(acc[i][1] + bias[i], 0.f);
                v.z = fmaxf(acc[i][2] + bias[i], 0.f);
                v.w = fmaxf(acc[i][3] + bias[i], 0.f);
                *(float4*)&g_h1[(b * 256 + co) * 400 + oy * 20 + oxb] = v;
            }
        }
    }
}

// ---------------------------------------------------------------------------
// conv2 (stride 2) + bias: grid (64, 8), block 288 (= 8 ty * 36 pos).
// Block: 8 images x 32 output channels x 36 positions.
// Thread tile: 4 channels x 8 images at one spatial position.
// K loop chunked over input channels (Cc=2), weights+inputs staged in smem.
// ---------------------------------------------------------------------------
__global__ __launch_bounds__(288) void k_conv2(const float* __restrict__ w2,
                                               const float* __restrict__ b2)
{
    __shared__ float ins[8][2][400];    // 25.6 KB: [img][cl][20*20]
    __shared__ float ws[32][162];       // 20.7 KB: [co_local][cl*81+k]
    const int ig = blockIdx.x;          // image group: b = ig*8 + g
    const int cg = blockIdx.y;          // channel group of 32
    const int id = threadIdx.x;
    const int ty = id & 7;              // co = cg*32 + ty + 8*i
    const int tx = id >> 3;             // 0..35: output position
    const int oy = tx / 6, ox = tx % 6;

    float acc[4][8];
#pragma unroll
    for (int i = 0; i < 4; i++)
#pragma unroll
        for (int g = 0; g < 8; g++) acc[i][g] = 0.f;

    for (int c0 = 0; c0 < 256; c0 += 2) {
        __syncthreads();
        // stage inputs: 8 imgs * 2 ch * 400 = 1600 float4
        for (int i = id; i < 1600; i += 288) {
            int flat = i * 4;
            int g    = flat / 800;
            int rem  = flat - g * 800;
            int cl   = rem / 400;
            int pix  = rem - cl * 400;
            *(float4*)&ins[g][cl][pix] =
                *(const float4*)&g_h1[((ig * 8 + g) * 256 + c0 + cl) * 400 + pix];
        }
        // stage weights: 32 co * 162 = 2592 float2 (c0 even -> float2 aligned)
        for (int i = id; i < 2592; i += 288) {
            int co = i / 81;
            int kk = (i - co * 81) * 2;
            *(float2*)&ws[co][kk] =
                *(const float2*)&w2[(cg * 32 + co) * 20736 + c0 * 81 + kk];
        }
        __syncthreads();

#pragma unroll 1
        for (int cl = 0; cl < 2; cl++) {
#pragma unroll 1
            for (int ky = 0; ky < 9; ky++) {
                const float* irow = &ins[0][cl][(2 * oy + ky) * 20 + 2 * ox];
                const int kb = cl * 81 + ky * 9;
#pragma unroll
                for (int kx = 0; kx < 9; kx++) {
                    float iv[8], wv[4];
#pragma unroll
                    for (int g = 0; g < 8; g++) iv[g] = irow[g * 800 + kx];
#pragma unroll
                    for (int i = 0; i < 4; i++) wv[i] = ws[ty + 8 * i][kb + kx];
#pragma unroll
                    for (int i = 0; i < 4; i++)
#pragma unroll
                        for (int g = 0; g < 8; g++)
                            acc[i][g] = fmaf(wv[i], iv[g], acc[i][g]);
                }
            }
        }
    }

#pragma unroll
    for (int i = 0; i < 4; i++) {
        int co = cg * 32 + ty + 8 * i;
        float bb = b2[co];
#pragma unroll
        for (int g = 0; g < 8; g++)
            g_h2[((ig * 8 + g) * 256 + co) * 36 + tx] = acc[i][g] + bb;
    }
}

// ---------------------------------------------------------------------------
// primary capsule squash: capsules are 8 consecutive floats in h2 flat.
// ---------------------------------------------------------------------------
__global__ __launch_bounds__(256) void k_squash_pc()
{
    unsigned idx = blockIdx.x * 256u + threadIdx.x;   // < 589824
    if (idx >= 589824u) return;
    const float4* p = (const float4*)(g_h2 + (size_t)idx * 8);
    float4 a = p[0], b = p[1];
    float sn = a.x*a.x + a.y*a.y + a.z*a.z + a.w*a.w
             + b.x*b.x + b.y*b.y + b.z*b.z + b.w*b.w;
    float sc = sn / ((1.f + sn) * (sqrtf(sn) + 1e-6f));
    a.x *= sc; a.y *= sc; a.z *= sc; a.w *= sc;
    b.x *= sc; b.y *= sc; b.z *= sc; b.w *= sc;
    float4* q = (float4*)(g_u + (size_t)idx * 8);
    q[0] = a; q[1] = b;
}

// ---------------------------------------------------------------------------
// u_hat: grid (288 cap-blocks of 4, 8 img-blocks of 64), block 256.
// u_hat[b,cap,o,e] = sum_d u[b,cap,d] * W[cap,o,d,e]
// ---------------------------------------------------------------------------
__global__ __launch_bounds__(256) void k_uhat(const float* __restrict__ W)
{
    __shared__ float Wsm[4 * 1280];     // 20.5 KB
    __shared__ float usm[64 * 32];      // 8.2 KB
    const int capg = blockIdx.x * 4;
    const int img0 = blockIdx.y * 64;
    const int id   = threadIdx.x;

    {
        const float4* Wg = (const float4*)(W + (size_t)capg * 1280);
        float4* Ws4 = (float4*)Wsm;
        for (int i = id; i < 1280; i += 256) Ws4[i] = Wg[i];
        float4* us4 = (float4*)usm;
        for (int i = id; i < 512; i += 256) {
            int im = i >> 3, r = i & 7;
            us4[i] = *(const float4*)(g_u + (size_t)(img0 + im) * 9216
                                      + capg * 8 + r * 4);
        }
    }
    __syncthreads();

    for (int it = 0; it < 40; it++) {
        int flat = it * 256 + id;       // < 64*4*40 = 10240
        int oe4  = flat % 40;
        int cap  = (flat / 40) & 3;
        int im   = flat / 160;
        int o    = oe4 >> 2;
        int e0   = (oe4 & 3) * 4;
        const float*  up = &usm[im * 32 + cap * 8];
        const float4* Wp = (const float4*)&Wsm[cap * 1280 + o * 128 + e0];
        float4 acc = make_float4(0.f, 0.f, 0.f, 0.f);
#pragma unroll
        for (int d = 0; d < 8; d++) {
            float  ud = up[d];
            float4 w4 = Wp[d * 4];
            acc.x = fmaf(ud, w4.x, acc.x);
            acc.y = fmaf(ud, w4.y, acc.y);
            acc.z = fmaf(ud, w4.z, acc.z);
            acc.w = fmaf(ud, w4.w, acc.w);
        }
        *(float4*)&g_uhat[((size_t)(img0 + im) * 1152 + capg + cap) * 160
                          + o * 16 + e0] = acc;
    }
}

// ---------------------------------------------------------------------------
// s[b,o,e] = sum_cap c[b,cap,o] * u_hat[b,cap,o,e]   (or uniform c = 0.1)
// grid 512, block 160 (thread = oe).
// ---------------------------------------------------------------------------
__global__ void k_reduce_s(int use_c)
{
    __shared__ float c_sm[11520];
    const int b  = blockIdx.x;
    const int oe = threadIdx.x;         // 0..159
    const int o  = oe >> 4;
    if (use_c) {
        const float4* cg4 = (const float4*)(g_c + (size_t)b * 11520);
        float4* cs4 = (float4*)c_sm;
        for (int i = threadIdx.x; i < 2880; i += 160) cs4[i] = cg4[i];
    }
    __syncthreads();
    const float* ub = g_uhat + (size_t)b * 184320;
    float acc = 0.f;
    if (use_c) {
#pragma unroll 4
        for (int cap = 0; cap < 1152; cap++)
            acc = fmaf(c_sm[cap * 10 + o], ub[cap * 160 + oe], acc);
    } else {
#pragma unroll 4
        for (int cap = 0; cap < 1152; cap++)
            acc += ub[cap * 160 + oe];
        acc *= 0.1f;
    }
    g_s[b * 160 + oe] = acc;
}

// ---------------------------------------------------------------------------
// squash of s -> v; mode 0: vsum = v; mode 1: vsum += v; mode 2: out = v
// ---------------------------------------------------------------------------
__global__ void k_squash_v(float* __restrict__ out, int mode)
{
    int idx = blockIdx.x * 256 + threadIdx.x;
    if (idx >= 5120) return;            // 512*10
    const float4* sp = (const float4*)(g_s + (size_t)idx * 16);
    float4 r[4];
    float sn = 0.f;
#pragma unroll
    for (int i = 0; i < 4; i++) {
        r[i] = sp[i];
        sn += r[i].x*r[i].x + r[i].y*r[i].y + r[i].z*r[i].z + r[i].w*r[i].w;
    }
    float sc = sn / ((1.f + sn) * (sqrtf(sn) + 1e-6f));
#pragma unroll
    for (int i = 0; i < 4; i++) {
        r[i].x *= sc; r[i].y *= sc; r[i].z *= sc; r[i].w *= sc;
    }
    if (mode == 0) {
        float4* q = (float4*)(g_vsum + (size_t)idx * 16);
#pragma unroll
        for (int i = 0; i < 4; i++) q[i] = r[i];
    } else if (mode == 1) {
        float4* q = (float4*)(g_vsum + (size_t)idx * 16);
#pragma unroll
        for (int i = 0; i < 4; i++) {
            float4 old = q[i];
            old.x += r[i].x; old.y += r[i].y; old.z += r[i].z; old.w += r[i].w;
            q[i] = old;
        }
    } else {
        float4* q = (float4*)(out + (size_t)idx * 16);
#pragma unroll
        for (int i = 0; i < 4; i++) q[i] = r[i];
    }
}

// ---------------------------------------------------------------------------
// logits + softmax: c[b,cap,:] = softmax_o( sum_e u_hat[b,cap,o,e]*vsum[b,o,e] )
// (valid because b_logits accumulates dot(u_hat, v_tau); vsum = sum of v's)
// ---------------------------------------------------------------------------
__global__ __launch_bounds__(256) void k_logits()
{
    unsigned idx = blockIdx.x * 256u + threadIdx.x;  // < 589824  (b*1152+cap)
    if (idx >= 589824u) return;
    int b = idx / 1152;
    const float4* uh = (const float4*)(g_uhat + (size_t)idx * 160);
    const float4* vs = (const float4*)(g_vsum + (size_t)b * 160);
    float t[10];
#pragma unroll
    for (int o = 0; o < 10; o++) {
        float sum = 0.f;
#pragma unroll
        for (int e4 = 0; e4 < 4; e4++) {
            float4 u4 = uh[o * 4 + e4];
            float4 v4 = vs[o * 4 + e4];
            sum += u4.x*v4.x + u4.y*v4.y + u4.z*v4.z + u4.w*v4.w;
        }
        t[o] = sum;
    }
    float m = t[0];
#pragma unroll
    for (int o = 1; o < 10; o++) m = fmaxf(m, t[o]);
    float se = 0.f;
#pragma unroll
    for (int o = 0; o < 10; o++) { t[o] = expf(t[o] - m); se += t[o]; }
    float inv = 1.f / se;
    float* cp = g_c + (size_t)idx * 10;
#pragma unroll
    for (int o = 0; o < 10; o++) cp[o] = t[o] * inv;
}

// ---------------------------------------------------------------------------
extern "C" void kernel_launch(void* const* d_in, const int* in_sizes, int n_in,
                              void* d_out, int out_size)
{
    const float* x   = (const float*)d_in[0];
    const float* w1  = (const float*)d_in[1];
    const float* b1  = (const float*)d_in[2];
    const float* w2  = (const float*)d_in[3];
    const float* b2  = (const float*)d_in[4];
    const float* W   = (const float*)d_in[5];
    float* out = (float*)d_out;

    k_conv1<<<dim3(512, 8), 256>>>(x, w1, b1);
    k_conv2<<<dim3(64, 8), 288>>>(w2, b2);
    k_squash_pc<<<2304, 256>>>();
    k_uhat<<<dim3(288, 8), 256>>>(W);

    // routing iteration 0 (uniform c = 0.1)
    k_reduce_s<<<512, 160>>>(0);
    k_squash_v<<<20, 256>>>(nullptr, 0);     // vsum = v0
    // iteration 1
    k_logits<<<2304, 256>>>();
    k_reduce_s<<<512, 160>>>(1);
    k_squash_v<<<20, 256>>>(nullptr, 1);     // vsum += v1
    // iteration 2 (final)
    k_logits<<<2304, 256>>>();
    k_reduce_s<<<512, 160>>>(1);
    k_squash_v<<<20, 256>>>(out, 2);         // out = v2
}

// round 3
// speedup vs baseline: 2.1796x; 2.1796x over previous
#include <cuda_runtime.h>
#include <cuda_bf16.h>
#include <cstdint>
#include <math.h>

// ===========================================================================
// CapsNet forward, B=512 — Round 3: conv2 via mma.sync (HMMA bf16, 3-term
// split). tcgen05 is unavailable: harness PTX targets compute_103 (no 'a'),
// which rejects all tcgen05/TMEM features. ldmatrix + mma.sync are baseline.
// ===========================================================================

// ------------------------------ scratch ------------------------------------
__device__ float          g_h1  [512u * 256u * 400u];      // 209.7 MB fp32 NCHW
__device__ __nv_bfloat16  g_h1t_hi[512u * 400u * 256u];    // 105 MB NHWC
__device__ __nv_bfloat16  g_h1t_lo[512u * 400u * 256u];
__device__ __nv_bfloat16  g_w2t_hi[81u * 256u * 256u];     // 10.6 MB
__device__ __nv_bfloat16  g_w2t_lo[81u * 256u * 256u];
__device__ float g_h2[512u * 9216u];
__device__ float g_u [512u * 9216u];
__device__ float g_uhat[512u * 1152u * 160u];
__device__ float g_c [512u * 1152u * 10u];
__device__ float g_s [512u * 160u];
__device__ float g_vsum[512u * 160u];

// ------------------------------ PTX helpers --------------------------------
__device__ __forceinline__ uint32_t smem_u32(const void* p) {
    uint32_t a;
    asm("{ .reg .u64 t; cvta.to.shared.u64 t, %1; cvt.u32.u64 %0, t; }"
        : "=r"(a) : "l"(p));
    return a;
}
#define CP16(dst, src) \
    asm volatile("cp.async.cg.shared.global [%0], [%1], 16;" :: "r"(dst), "l"(src) : "memory")
#define CP_COMMIT() asm volatile("cp.async.commit_group;" ::: "memory")
#define CP_WAIT1()  asm volatile("cp.async.wait_group 1;" ::: "memory")
#define CP_WAIT0()  asm volatile("cp.async.wait_group 0;" ::: "memory")

__device__ __forceinline__ void ldsm_x4(uint32_t* r, uint32_t addr) {
    asm volatile("ldmatrix.sync.aligned.m8n8.x4.shared.b16 {%0,%1,%2,%3}, [%4];"
                 : "=r"(r[0]), "=r"(r[1]), "=r"(r[2]), "=r"(r[3]) : "r"(addr));
}
__device__ __forceinline__ void ldsm_x2(uint32_t* r, uint32_t addr) {
    asm volatile("ldmatrix.sync.aligned.m8n8.x2.shared.b16 {%0,%1}, [%2];"
                 : "=r"(r[0]), "=r"(r[1]) : "r"(addr));
}
__device__ __forceinline__ void mma16816(float* c, const uint32_t* a,
                                         const uint32_t* b) {
    asm volatile("mma.sync.aligned.m16n8k16.row.col.f32.bf16.bf16.f32 "
                 "{%0,%1,%2,%3}, {%4,%5,%6,%7}, {%8,%9}, {%0,%1,%2,%3};"
                 : "+f"(c[0]), "+f"(c[1]), "+f"(c[2]), "+f"(c[3])
                 : "r"(a[0]), "r"(a[1]), "r"(a[2]), "r"(a[3]),
                   "r"(b[0]), "r"(b[1]));
}
__device__ __forceinline__ uint32_t swz(uint32_t o) {
    return o ^ ((o >> 3) & 0x70);
}

// ---------------------------------------------------------------------------
// conv1 + relu (unchanged)
// ---------------------------------------------------------------------------
__global__ __launch_bounds__(256) void k_conv1(const float* __restrict__ x,
                                               const float* __restrict__ w1,
                                               const float* __restrict__ b1)
{
    __shared__ float xs[2352];
    __shared__ float ws[7776];
    const int b  = blockIdx.x;
    const int cg = blockIdx.y;
    const int id = threadIdx.x;
    {
        const float4* xg = (const float4*)(x + b * 2352);
        float4* xs4 = (float4*)xs;
        for (int i = id; i < 588; i += 256) xs4[i] = xg[i];
        const float4* wg = (const float4*)(w1 + cg * 7776);
        float4* ws4 = (float4*)ws;
        for (int i = id; i < 1944; i += 256) ws4[i] = wg[i];
    }
    __syncthreads();
    const int ty = id & 3;
    const int tx = id >> 2;
    float bias[8];
#pragma unroll
    for (int i = 0; i < 8; i++) bias[i] = b1[cg * 32 + ty + 4 * i];

    for (int qi = 0; qi < 2; qi++) {
        int gq = tx + 64 * qi;
        if (gq < 100) {
            int oy  = gq / 5;
            int oxb = (gq % 5) * 4;
            float acc[8][4];
#pragma unroll
            for (int i = 0; i < 8; i++)
#pragma unroll
                for (int j = 0; j < 4; j++) acc[i][j] = 0.f;
            for (int c = 0; c < 3; c++) {
                for (int ky = 0; ky < 9; ky++) {
                    const float* xrow = &xs[(c * 28 + oy + ky) * 28 + oxb];
                    float rin[12];
                    *(float4*)(rin)     = *(const float4*)(xrow);
                    *(float4*)(rin + 4) = *(const float4*)(xrow + 4);
                    *(float4*)(rin + 8) = *(const float4*)(xrow + 8);
                    const int kb = c * 81 + ky * 9;
#pragma unroll
                    for (int kx = 0; kx < 9; kx++) {
#pragma unroll
                        for (int i = 0; i < 8; i++) {
                            float w = ws[(ty + 4 * i) * 243 + kb + kx];
                            acc[i][0] = fmaf(w, rin[kx],     acc[i][0]);
                            acc[i][1] = fmaf(w, rin[kx + 1], acc[i][1]);
                            acc[i][2] = fmaf(w, rin[kx + 2], acc[i][2]);
                            acc[i][3] = fmaf(w, rin[kx + 3], acc[i][3]);
                        }
                    }
                }
            }
#pragma unroll
            for (int i = 0; i < 8; i++) {
                int co = cg * 32 + ty + 4 * i;
                float4 v;
                v.x = fmaxf(acc[i][0] + bias[i], 0.f);
                v.y = fmaxf(acc[i][1] + bias[i], 0.f);
                v.z = fmaxf(acc[i][2] + bias[i], 0.f);
                v.w = fmaxf(acc[i][3] + bias[i], 0.f);
                *(float4*)&g_h1[(b * 256 + co) * 400 + oy * 20 + oxb] = v;
            }
        }
    }
}

// ---------------------------------------------------------------------------
// h1 NCHW fp32 -> NHWC bf16 hi/lo (unchanged)
// ---------------------------------------------------------------------------
__global__ __launch_bounds__(256) void k_tobf16()
{
    __shared__ float s[256][17];
    const int b  = blockIdx.x;
    const int p0 = blockIdx.y * 16;
    const int id = threadIdx.x;
    const int c  = id >> 2;
    const int q4 = (id & 3) * 4;
#pragma unroll
    for (int q = 0; q < 4; q++) {
        float4 v = *(const float4*)&g_h1[((size_t)b * 256 + c + q * 64) * 400 + p0 + q4];
        s[c + q * 64][q4] = v.x; s[c + q * 64][q4 + 1] = v.y;
        s[c + q * 64][q4 + 2] = v.z; s[c + q * 64][q4 + 3] = v.w;
    }
    __syncthreads();
    const int pix = id >> 4;
    const int c0  = (id & 15) * 16;
    __align__(16) __nv_bfloat16 hb[16], lb[16];
#pragma unroll
    for (int i = 0; i < 16; i++) {
        float v = s[c0 + i][pix];
        __nv_bfloat16 h = __float2bfloat16(v);
        hb[i] = h;
        lb[i] = __float2bfloat16(v - __bfloat162float(h));
    }
    size_t dst = ((size_t)b * 400 + p0 + pix) * 256 + c0;
    ((uint4*)&g_h1t_hi[dst])[0] = ((uint4*)hb)[0];
    ((uint4*)&g_h1t_hi[dst])[1] = ((uint4*)hb)[1];
    ((uint4*)&g_h1t_lo[dst])[0] = ((uint4*)lb)[0];
    ((uint4*)&g_h1t_lo[dst])[1] = ((uint4*)lb)[1];
}

// ---------------------------------------------------------------------------
// W2 [co][c][9][9] -> [kykx][co][c] bf16 hi/lo (unchanged)
// ---------------------------------------------------------------------------
__global__ __launch_bounds__(256) void k_wprep(const float* __restrict__ w2)
{
    const int kk  = blockIdx.x;
    const int co0 = blockIdx.y * 32;
    const int c   = threadIdx.x;
    for (int i = 0; i < 32; i++) {
        int co = co0 + i;
        float v = w2[(size_t)co * 20736 + c * 81 + kk];
        __nv_bfloat16 h = __float2bfloat16(v);
        size_t d = ((size_t)kk * 256 + co) * 256 + c;
        g_w2t_hi[d] = h;
        g_w2t_lo[d] = __float2bfloat16(v - __bfloat162float(h));
    }
}

// ---------------------------------------------------------------------------
// conv2 implicit GEMM via mma.sync. grid (72, 2), block 256, 196608 B smem.
// CTA tile: M=128 co x N=256 positions. 324 K64 chunks (81 taps x 4 c-chunks).
// Warps: 2(M) x 4(N); warp tile 64x64; m16n8k16 bf16, fp32 accum in regs.
// Terms: Ah*Bh + Ah*Bl + Al*Bh.
// Stage (96KB): Ah[16K] Al[16K] Bh[32K] Bl[32K]; 2 stages, cp.async pipeline.
// ---------------------------------------------------------------------------
#define STAGE_BYTES 98304
#define AH_OFF 0
#define AL_OFF 16384
#define BH_OFF 32768
#define BL_OFF 65536
#define NCHUNK 324

__device__ __forceinline__ void load_chunk(
    uint32_t stbase, int kk, int c0, int tid, int arow,
    const __nv_bfloat16* wsrc, uint32_t adst_off,
    int bimg, int oy, int ox, int coBase)
{
    const int ky = kk / 9, kx = kk - ky * 9;
    const __nv_bfloat16* aS =
        wsrc + ((size_t)kk * 256 + coBase + arow) * 256 + c0;
    const size_t pix = (size_t)bimg * 400 + (2 * oy + ky) * 20 + (2 * ox + kx);
    const __nv_bfloat16* bSh = g_h1t_hi + pix * 256 + c0;
    const __nv_bfloat16* bSl = g_h1t_lo + pix * 256 + c0;
    const uint32_t aD  = stbase + adst_off;
    const uint32_t bDh = stbase + BH_OFF;
    const uint32_t bDl = stbase + BL_OFF;
#pragma unroll
    for (int u = 0; u < 8; u++) {
        uint32_t oa = swz(arow * 128 + u * 16);
        CP16(aD + oa, aS + u * 8);
        uint32_t ob = swz(tid * 128 + u * 16);
        CP16(bDh + ob, bSh + u * 8);
        CP16(bDl + ob, bSl + u * 8);
    }
}

__global__ __launch_bounds__(256) void k_conv2mma(const float* __restrict__ b2)
{
    extern __shared__ __align__(1024) char dynsmem[];
    const uint32_t sb = smem_u32(dynsmem);
    const int tid  = threadIdx.x;
    const int warp = tid >> 5;
    const int lane = tid & 31;
    const int n0     = blockIdx.x * 256;
    const int coBase = blockIdx.y * 128;
    const int mwarp = warp & 1;      // 0..1 : co half of 64
    const int nwarp = warp >> 1;     // 0..3 : n quarter of 64

    // staging role (fixed per thread)
    const int arow = tid & 127;
    const __nv_bfloat16* wsrc = (tid < 128) ? g_w2t_hi : g_w2t_lo;
    const uint32_t adst_off   = (tid < 128) ? AH_OFF : AL_OFF;
    const int nB   = n0 + tid;
    const int bimg = nB / 36;
    const int pos  = nB - bimg * 36;
    const int oy   = pos / 6, ox = pos - oy * 6;

    // ldmatrix per-lane address components
    const int l15      = lane & 15;
    const int bRowSub  = l15 & 7;              // row within n8 frag
    const int bColSel  = (l15 >> 3) * 16;      // k half selector (bytes)
    const int aRowSub  = l15;                  // row within m16 frag
    const int aColSel  = (lane >> 4) * 16;     // k half selector (bytes)

    float acc[4][8][4];
#pragma unroll
    for (int mf = 0; mf < 4; mf++)
#pragma unroll
        for (int nf = 0; nf < 8; nf++)
#pragma unroll
            for (int i = 0; i < 4; i++) acc[mf][nf][i] = 0.f;

    // prologue
    load_chunk(sb, 0, 0, tid, arow, wsrc, adst_off, bimg, oy, ox, coBase);
    CP_COMMIT();

    for (int t = 0; t < NCHUNK; t++) {
        const int s = t & 1, s2 = s ^ 1;
        if (t + 1 < NCHUNK) {
            const int tn = t + 1;
            load_chunk(sb + s2 * STAGE_BYTES, tn >> 2, (tn & 3) * 64,
                       tid, arow, wsrc, adst_off, bimg, oy, ox, coBase);
            CP_COMMIT();
            CP_WAIT1();
        } else {
            CP_WAIT0();
        }
        __syncthreads();

        const uint32_t stb = sb + s * STAGE_BYTES;
        const uint32_t ah = stb + AH_OFF, al = stb + AL_OFF;
        const uint32_t bh = stb + BH_OFF, bl = stb + BL_OFF;

#pragma unroll
        for (int q = 0; q < 4; q++) {
            const int qb = q * 32;
#pragma unroll
            for (int g = 0; g < 2; g++) {        // n-frag group of 4
                uint32_t Bh[4][2], Bl[4][2];
#pragma unroll
                for (int nf = 0; nf < 4; nf++) {
                    uint32_t off = swz((nwarp * 64 + (g * 4 + nf) * 8 + bRowSub) * 128
                                       + qb + bColSel);
                    ldsm_x2(Bh[nf], bh + off);
                    ldsm_x2(Bl[nf], bl + off);
                }
#pragma unroll
                for (int mf = 0; mf < 4; mf++) {
                    uint32_t Ah[4], Al[4];
                    uint32_t offA = swz((mwarp * 64 + mf * 16 + aRowSub) * 128
                                        + qb + aColSel);
                    ldsm_x4(Ah, ah + offA);
                    ldsm_x4(Al, al + offA);
#pragma unroll
                    for (int nf = 0; nf < 4; nf++) {
                        float* c = acc[mf][g * 4 + nf];
                        mma16816(c, Ah, Bh[nf]);
                        mma16816(c, Ah, Bl[nf]);
                        mma16816(c, Al, Bh[nf]);
                    }
                }
            }
        }
        __syncthreads();
    }

    // epilogue: bias + store to h2 [b][co][pos]
#pragma unroll
    for (int mf = 0; mf < 4; mf++) {
        const int coB = coBase + mwarp * 64 + mf * 16 + (lane >> 2);
        const float bias0 = b2[coB];
        const float bias1 = b2[coB + 8];
#pragma unroll
        for (int nf = 0; nf < 8; nf++) {
#pragma unroll
            for (int i = 0; i < 4; i++) {
                const int co = coB + ((i >> 1) << 3);
                const int n  = n0 + nwarp * 64 + nf * 8 + ((lane & 3) << 1) + (i & 1);
                const int bi = n / 36;
                const int pp = n - bi * 36;
                g_h2[(size_t)bi * 9216 + co * 36 + pp] =
                    acc[mf][nf][i] + ((i >> 1) ? bias1 : bias0);
            }
        }
    }
}

// ---------------------------------------------------------------------------
// primary capsule squash (unchanged)
// ---------------------------------------------------------------------------
__global__ __launch_bounds__(256) void k_squash_pc()
{
    unsigned idx = blockIdx.x * 256u + threadIdx.x;
    if (idx >= 589824u) return;
    const float4* p = (const float4*)(g_h2 + (size_t)idx * 8);
    float4 a = p[0], b = p[1];
    float sn = a.x*a.x + a.y*a.y + a.z*a.z + a.w*a.w
             + b.x*b.x + b.y*b.y + b.z*b.z + b.w*b.w;
    float sc = sn / ((1.f + sn) * (sqrtf(sn) + 1e-6f));
    a.x *= sc; a.y *= sc; a.z *= sc; a.w *= sc;
    b.x *= sc; b.y *= sc; b.z *= sc; b.w *= sc;
    float4* q = (float4*)(g_u + (size_t)idx * 8);
    q[0] = a; q[1] = b;
}

// ---------------------------------------------------------------------------
// u_hat (unchanged)
// ---------------------------------------------------------------------------
__global__ __launch_bounds__(256) void k_uhat(const float* __restrict__ W)
{
    __shared__ float Wsm[4 * 1280];
    __shared__ float usm[64 * 32];
    const int capg = blockIdx.x * 4;
    const int img0 = blockIdx.y * 64;
    const int id   = threadIdx.x;
    {
        const float4* Wg = (const float4*)(W + (size_t)capg * 1280);
        float4* Ws4 = (float4*)Wsm;
        for (int i = id; i < 1280; i += 256) Ws4[i] = Wg[i];
        float4* us4 = (float4*)usm;
        for (int i = id; i < 512; i += 256) {
            int im = i >> 3, r = i & 7;
            us4[i] = *(const float4*)(g_u + (size_t)(img0 + im) * 9216
                                      + capg * 8 + r * 4);
        }
    }
    __syncthreads();
    for (int it = 0; it < 40; it++) {
        int flat = it * 256 + id;
        int oe4  = flat % 40;
        int cap  = (flat / 40) & 3;
        int im   = flat / 160;
        int o    = oe4 >> 2;
        int e0   = (oe4 & 3) * 4;
        const float*  up = &usm[im * 32 + cap * 8];
        const float4* Wp = (const float4*)&Wsm[cap * 1280 + o * 128 + e0];
        float4 acc = make_float4(0.f, 0.f, 0.f, 0.f);
#pragma unroll
        for (int d = 0; d < 8; d++) {
            float  ud = up[d];
            float4 w4 = Wp[d * 4];
            acc.x = fmaf(ud, w4.x, acc.x);
            acc.y = fmaf(ud, w4.y, acc.y);
            acc.z = fmaf(ud, w4.z, acc.z);
            acc.w = fmaf(ud, w4.w, acc.w);
        }
        *(float4*)&g_uhat[((size_t)(img0 + im) * 1152 + capg + cap) * 160
                          + o * 16 + e0] = acc;
    }
}

// ---------------------------------------------------------------------------
// routing kernels (unchanged)
// ---------------------------------------------------------------------------
__global__ void k_reduce_s(int use_c)
{
    __shared__ float c_sm[11520];
    const int b  = blockIdx.x;
    const int oe = threadIdx.x;
    const int o  = oe >> 4;
    if (use_c) {
        const float4* cg4 = (const float4*)(g_c + (size_t)b * 11520);
        float4* cs4 = (float4*)c_sm;
        for (int i = threadIdx.x; i < 2880; i += 160) cs4[i] = cg4[i];
    }
    __syncthreads();
    const float* ub = g_uhat + (size_t)b * 184320;
    float acc = 0.f;
    if (use_c) {
#pragma unroll 4
        for (int cap = 0; cap < 1152; cap++)
            acc = fmaf(c_sm[cap * 10 + o], ub[cap * 160 + oe], acc);
    } else {
#pragma unroll 4
        for (int cap = 0; cap < 1152; cap++)
            acc += ub[cap * 160 + oe];
        acc *= 0.1f;
    }
    g_s[b * 160 + oe] = acc;
}

__global__ void k_squash_v(float* __restrict__ out, int mode)
{
    int idx = blockIdx.x * 256 + threadIdx.x;
    if (idx >= 5120) return;
    const float4* sp = (const float4*)(g_s + (size_t)idx * 16);
    float4 r[4];
    float sn = 0.f;
#pragma unroll
    for (int i = 0; i < 4; i++) {
        r[i] = sp[i];
        sn += r[i].x*r[i].x + r[i].y*r[i].y + r[i].z*r[i].z + r[i].w*r[i].w;
    }
    float sc = sn / ((1.f + sn) * (sqrtf(sn) + 1e-6f));
#pragma unroll
    for (int i = 0; i < 4; i++) {
        r[i].x *= sc; r[i].y *= sc; r[i].z *= sc; r[i].w *= sc;
    }
    if (mode == 0) {
        float4* q = (float4*)(g_vsum + (size_t)idx * 16);
#pragma unroll
        for (int i = 0; i < 4; i++) q[i] = r[i];
    } else if (mode == 1) {
        float4* q = (float4*)(g_vsum + (size_t)idx * 16);
#pragma unroll
        for (int i = 0; i < 4; i++) {
            float4 old = q[i];
            old.x += r[i].x; old.y += r[i].y; old.z += r[i].z; old.w += r[i].w;
            q[i] = old;
        }
    } else {
        float4* q = (float4*)(out + (size_t)idx * 16);
#pragma unroll
        for (int i = 0; i < 4; i++) q[i] = r[i];
    }
}

__global__ __launch_bounds__(256) void k_logits()
{
    unsigned idx = blockIdx.x * 256u + threadIdx.x;
    if (idx >= 589824u) return;
    int b = idx / 1152;
    const float4* uh = (const float4*)(g_uhat + (size_t)idx * 160);
    const float4* vs = (const float4*)(g_vsum + (size_t)b * 160);
    float t[10];
#pragma unroll
    for (int o = 0; o < 10; o++) {
        float sum = 0.f;
#pragma unroll
        for (int e4 = 0; e4 < 4; e4++) {
            float4 u4 = uh[o * 4 + e4];
            float4 v4 = vs[o * 4 + e4];
            sum += u4.x*v4.x + u4.y*v4.y + u4.z*v4.z + u4.w*v4.w;
        }
        t[o] = sum;
    }
    float m = t[0];
#pragma unroll
    for (int o = 1; o < 10; o++) m = fmaxf(m, t[o]);
    float se = 0.f;
#pragma unroll
    for (int o = 0; o < 10; o++) { t[o] = expf(t[o] - m); se += t[o]; }
    float inv = 1.f / se;
    float* cp = g_c + (size_t)idx * 10;
#pragma unroll
    for (int o = 0; o < 10; o++) cp[o] = t[o] * inv;
}

// ---------------------------------------------------------------------------
extern "C" void kernel_launch(void* const* d_in, const int* in_sizes, int n_in,
                              void* d_out, int out_size)
{
    const float* x   = (const float*)d_in[0];
    const float* w1  = (const float*)d_in[1];
    const float* b1  = (const float*)d_in[2];
    const float* w2  = (const float*)d_in[3];
    const float* b2  = (const float*)d_in[4];
    const float* W   = (const float*)d_in[5];
    float* out = (float*)d_out;

    cudaFuncSetAttribute(k_conv2mma,
                         cudaFuncAttributeMaxDynamicSharedMemorySize, 196608);

    k_conv1<<<dim3(512, 8), 256>>>(x, w1, b1);
    k_wprep<<<dim3(81, 8), 256>>>(w2);
    k_tobf16<<<dim3(512, 25), 256>>>();
    k_conv2mma<<<dim3(72, 2), 256, 196608>>>(b2);
    k_squash_pc<<<2304, 256>>>();
    k_uhat<<<dim3(288, 8), 256>>>(W);

    k_reduce_s<<<512, 160>>>(0);
    k_squash_v<<<20, 256>>>(nullptr, 0);
    k_logits<<<2304, 256>>>();
    k_reduce_s<<<512, 160>>>(1);
    k_squash_v<<<20, 256>>>(nullptr, 1);
    k_logits<<<2304, 256>>>();
    k_reduce_s<<<512, 160>>>(1);
    k_squash_v<<<20, 256>>>(out, 2);
}

// round 4
// speedup vs baseline: 2.3902x; 1.0966x over previous
#include <cuda_runtime.h>
#include <cuda_bf16.h>
#include <cuda_fp16.h>
#include <cstdint>
#include <math.h>

// ===========================================================================
// CapsNet forward, B=512 — Round 4: fp16 u_hat + fused routing (one DRAM
// pass per iteration), conv2 mma.sync with merged B ldmatrix.x4.
// ===========================================================================

// ------------------------------ scratch ------------------------------------
__device__ float          g_h1  [512u * 256u * 400u];      // 209.7 MB fp32 NCHW
__device__ __nv_bfloat16  g_h1t_hi[512u * 400u * 256u];    // 105 MB NHWC
__device__ __nv_bfloat16  g_h1t_lo[512u * 400u * 256u];
__device__ __nv_bfloat16  g_w2t_hi[81u * 256u * 256u];     // 10.6 MB
__device__ __nv_bfloat16  g_w2t_lo[81u * 256u * 256u];
__device__ float  g_h2[512u * 9216u];
__device__ float  g_u [512u * 9216u];
__device__ __half g_uhat_h[512u * 1152u * 160u];           // 188.7 MB fp16
__device__ float  g_spart[9u * 512u * 160u];               // partial s sums
__device__ float  g_vsum[512u * 160u];

// ------------------------------ PTX helpers --------------------------------
__device__ __forceinline__ uint32_t smem_u32(const void* p) {
    uint32_t a;
    asm("{ .reg .u64 t; cvta.to.shared.u64 t, %1; cvt.u32.u64 %0, t; }"
        : "=r"(a) : "l"(p));
    return a;
}
#define CP16(dst, src) \
    asm volatile("cp.async.cg.shared.global [%0], [%1], 16;" :: "r"(dst), "l"(src) : "memory")
#define CP_COMMIT() asm volatile("cp.async.commit_group;" ::: "memory")
#define CP_WAIT1()  asm volatile("cp.async.wait_group 1;" ::: "memory")
#define CP_WAIT0()  asm volatile("cp.async.wait_group 0;" ::: "memory")

__device__ __forceinline__ void ldsm_x4(uint32_t* r, uint32_t addr) {
    asm volatile("ldmatrix.sync.aligned.m8n8.x4.shared.b16 {%0,%1,%2,%3}, [%4];"
                 : "=r"(r[0]), "=r"(r[1]), "=r"(r[2]), "=r"(r[3]) : "r"(addr));
}
__device__ __forceinline__ void mma16816(float* c, const uint32_t* a,
                                         const uint32_t* b) {
    asm volatile("mma.sync.aligned.m16n8k16.row.col.f32.bf16.bf16.f32 "
                 "{%0,%1,%2,%3}, {%4,%5,%6,%7}, {%8,%9}, {%0,%1,%2,%3};"
                 : "+f"(c[0]), "+f"(c[1]), "+f"(c[2]), "+f"(c[3])
                 : "r"(a[0]), "r"(a[1]), "r"(a[2]), "r"(a[3]),
                   "r"(b[0]), "r"(b[1]));
}
__device__ __forceinline__ uint32_t swz(uint32_t o) {
    return o ^ ((o >> 3) & 0x70);
}

// ---------------------------------------------------------------------------
// conv1 + relu (unchanged)
// ---------------------------------------------------------------------------
__global__ __launch_bounds__(256) void k_conv1(const float* __restrict__ x,
                                               const float* __restrict__ w1,
                                               const float* __restrict__ b1)
{
    __shared__ float xs[2352];
    __shared__ float ws[7776];
    const int b  = blockIdx.x;
    const int cg = blockIdx.y;
    const int id = threadIdx.x;
    {
        const float4* xg = (const float4*)(x + b * 2352);
        float4* xs4 = (float4*)xs;
        for (int i = id; i < 588; i += 256) xs4[i] = xg[i];
        const float4* wg = (const float4*)(w1 + cg * 7776);
        float4* ws4 = (float4*)ws;
        for (int i = id; i < 1944; i += 256) ws4[i] = wg[i];
    }
    __syncthreads();
    const int ty = id & 3;
    const int tx = id >> 2;
    float bias[8];
#pragma unroll
    for (int i = 0; i < 8; i++) bias[i] = b1[cg * 32 + ty + 4 * i];

    for (int qi = 0; qi < 2; qi++) {
        int gq = tx + 64 * qi;
        if (gq < 100) {
            int oy  = gq / 5;
            int oxb = (gq % 5) * 4;
            float acc[8][4];
#pragma unroll
            for (int i = 0; i < 8; i++)
#pragma unroll
                for (int j = 0; j < 4; j++) acc[i][j] = 0.f;
            for (int c = 0; c < 3; c++) {
                for (int ky = 0; ky < 9; ky++) {
                    const float* xrow = &xs[(c * 28 + oy + ky) * 28 + oxb];
                    float rin[12];
                    *(float4*)(rin)     = *(const float4*)(xrow);
                    *(float4*)(rin + 4) = *(const float4*)(xrow + 4);
                    *(float4*)(rin + 8) = *(const float4*)(xrow + 8);
                    const int kb = c * 81 + ky * 9;
#pragma unroll
                    for (int kx = 0; kx < 9; kx++) {
#pragma unroll
                        for (int i = 0; i < 8; i++) {
                            float w = ws[(ty + 4 * i) * 243 + kb + kx];
                            acc[i][0] = fmaf(w, rin[kx],     acc[i][0]);
                            acc[i][1] = fmaf(w, rin[kx + 1], acc[i][1]);
                            acc[i][2] = fmaf(w, rin[kx + 2], acc[i][2]);
                            acc[i][3] = fmaf(w, rin[kx + 3], acc[i][3]);
                        }
                    }
                }
            }
#pragma unroll
            for (int i = 0; i < 8; i++) {
                int co = cg * 32 + ty + 4 * i;
                float4 v;
                v.x = fmaxf(acc[i][0] + bias[i], 0.f);
                v.y = fmaxf(acc[i][1] + bias[i], 0.f);
                v.z = fmaxf(acc[i][2] + bias[i], 0.f);
                v.w = fmaxf(acc[i][3] + bias[i], 0.f);
                *(float4*)&g_h1[(b * 256 + co) * 400 + oy * 20 + oxb] = v;
            }
        }
    }
}

// ---------------------------------------------------------------------------
// h1 NCHW fp32 -> NHWC bf16 hi/lo (unchanged)
// ---------------------------------------------------------------------------
__global__ __launch_bounds__(256) void k_tobf16()
{
    __shared__ float s[256][17];
    const int b  = blockIdx.x;
    const int p0 = blockIdx.y * 16;
    const int id = threadIdx.x;
    const int c  = id >> 2;
    const int q4 = (id & 3) * 4;
#pragma unroll
    for (int q = 0; q < 4; q++) {
        float4 v = *(const float4*)&g_h1[((size_t)b * 256 + c + q * 64) * 400 + p0 + q4];
        s[c + q * 64][q4] = v.x; s[c + q * 64][q4 + 1] = v.y;
        s[c + q * 64][q4 + 2] = v.z; s[c + q * 64][q4 + 3] = v.w;
    }
    __syncthreads();
    const int pix = id >> 4;
    const int c0  = (id & 15) * 16;
    __align__(16) __nv_bfloat16 hb[16], lb[16];
#pragma unroll
    for (int i = 0; i < 16; i++) {
        float v = s[c0 + i][pix];
        __nv_bfloat16 h = __float2bfloat16(v);
        hb[i] = h;
        lb[i] = __float2bfloat16(v - __bfloat162float(h));
    }
    size_t dst = ((size_t)b * 400 + p0 + pix) * 256 + c0;
    ((uint4*)&g_h1t_hi[dst])[0] = ((uint4*)hb)[0];
    ((uint4*)&g_h1t_hi[dst])[1] = ((uint4*)hb)[1];
    ((uint4*)&g_h1t_lo[dst])[0] = ((uint4*)lb)[0];
    ((uint4*)&g_h1t_lo[dst])[1] = ((uint4*)lb)[1];
}

// ---------------------------------------------------------------------------
// W2 [co][c][9][9] -> [kykx][co][c] bf16 hi/lo (unchanged)
// ---------------------------------------------------------------------------
__global__ __launch_bounds__(256) void k_wprep(const float* __restrict__ w2)
{
    const int kk  = blockIdx.x;
    const int co0 = blockIdx.y * 32;
    const int c   = threadIdx.x;
    for (int i = 0; i < 32; i++) {
        int co = co0 + i;
        float v = w2[(size_t)co * 20736 + c * 81 + kk];
        __nv_bfloat16 h = __float2bfloat16(v);
        size_t d = ((size_t)kk * 256 + co) * 256 + c;
        g_w2t_hi[d] = h;
        g_w2t_lo[d] = __float2bfloat16(v - __bfloat162float(h));
    }
}

// ---------------------------------------------------------------------------
// conv2 implicit GEMM via mma.sync. grid (72, 2), block 256, 196608 B smem.
// ---------------------------------------------------------------------------
#define STAGE_BYTES 98304
#define AH_OFF 0
#define AL_OFF 16384
#define BH_OFF 32768
#define BL_OFF 65536
#define NCHUNK 324

__device__ __forceinline__ void load_chunk(
    uint32_t stbase, int kk, int c0, int tid, int arow,
    const __nv_bfloat16* wsrc, uint32_t adst_off,
    int bimg, int oy, int ox, int coBase)
{
    const int ky = kk / 9, kx = kk - ky * 9;
    const __nv_bfloat16* aS =
        wsrc + ((size_t)kk * 256 + coBase + arow) * 256 + c0;
    const size_t pix = (size_t)bimg * 400 + (2 * oy + ky) * 20 + (2 * ox + kx);
    const __nv_bfloat16* bSh = g_h1t_hi + pix * 256 + c0;
    const __nv_bfloat16* bSl = g_h1t_lo + pix * 256 + c0;
    const uint32_t aD  = stbase + adst_off;
    const uint32_t bDh = stbase + BH_OFF;
    const uint32_t bDl = stbase + BL_OFF;
#pragma unroll
    for (int u = 0; u < 8; u++) {
        uint32_t oa = swz(arow * 128 + u * 16);
        CP16(aD + oa, aS + u * 8);
        uint32_t ob = swz(tid * 128 + u * 16);
        CP16(bDh + ob, bSh + u * 8);
        CP16(bDl + ob, bSl + u * 8);
    }
}

__global__ __launch_bounds__(256) void k_conv2mma(const float* __restrict__ b2)
{
    extern __shared__ __align__(1024) char dynsmem[];
    const uint32_t sb = smem_u32(dynsmem);
    const int tid  = threadIdx.x;
    const int warp = tid >> 5;
    const int lane = tid & 31;
    const int n0     = blockIdx.x * 256;
    const int coBase = blockIdx.y * 128;
    const int mwarp = warp & 1;
    const int nwarp = warp >> 1;

    const int arow = tid & 127;
    const __nv_bfloat16* wsrc = (tid < 128) ? g_w2t_hi : g_w2t_lo;
    const uint32_t adst_off   = (tid < 128) ? AH_OFF : AL_OFF;
    const int nB   = n0 + tid;
    const int bimg = nB / 36;
    const int pos  = nB - bimg * 36;
    const int oy   = pos / 6, ox = pos - oy * 6;

    // ldmatrix lane addressing
    const int l15     = lane & 15;
    const int aRowSub = l15;
    const int aColSel = (lane >> 4) * 16;
    // B x4 (two n8 frags per load): mat = lane>>3
    const int bMat    = lane >> 3;         // 0..3
    const int bSub    = lane & 7;
    const int bNfSel  = bMat >> 1;         // which frag of the pair
    const int bKSel   = (bMat & 1) * 16;   // k half (bytes)

    float acc[4][8][4];
#pragma unroll
    for (int mf = 0; mf < 4; mf++)
#pragma unroll
        for (int nf = 0; nf < 8; nf++)
#pragma unroll
            for (int i = 0; i < 4; i++) acc[mf][nf][i] = 0.f;

    load_chunk(sb, 0, 0, tid, arow, wsrc, adst_off, bimg, oy, ox, coBase);
    CP_COMMIT();

    for (int t = 0; t < NCHUNK; t++) {
        const int s = t & 1, s2 = s ^ 1;
        if (t + 1 < NCHUNK) {
            const int tn = t + 1;
            load_chunk(sb + s2 * STAGE_BYTES, tn >> 2, (tn & 3) * 64,
                       tid, arow, wsrc, adst_off, bimg, oy, ox, coBase);
            CP_COMMIT();
            CP_WAIT1();
        } else {
            CP_WAIT0();
        }
        __syncthreads();

        const uint32_t stb = sb + s * STAGE_BYTES;
        const uint32_t ah = stb + AH_OFF, al = stb + AL_OFF;
        const uint32_t bh = stb + BH_OFF, bl = stb + BL_OFF;

#pragma unroll
        for (int q = 0; q < 4; q++) {
            const int qb = q * 32;
#pragma unroll
            for (int g = 0; g < 2; g++) {
                uint32_t Bh[4][2], Bl[4][2];
#pragma unroll
                for (int p = 0; p < 2; p++) {
                    const int nf = p * 2 + bNfSel;
                    uint32_t off = swz((nwarp * 64 + (g * 4 + nf) * 8 + bSub) * 128
                                       + qb + bKSel);
                    uint32_t r[4];
                    ldsm_x4(r, bh + off);
                    Bh[p*2][0] = r[0]; Bh[p*2][1] = r[1];
                    Bh[p*2+1][0] = r[2]; Bh[p*2+1][1] = r[3];
                    ldsm_x4(r, bl + off);
                    Bl[p*2][0] = r[0]; Bl[p*2][1] = r[1];
                    Bl[p*2+1][0] = r[2]; Bl[p*2+1][1] = r[3];
                }
#pragma unroll
                for (int mf = 0; mf < 4; mf++) {
                    uint32_t Ah[4], Al[4];
                    uint32_t offA = swz((mwarp * 64 + mf * 16 + aRowSub) * 128
                                        + qb + aColSel);
                    ldsm_x4(Ah, ah + offA);
                    ldsm_x4(Al, al + offA);
#pragma unroll
                    for (int nf = 0; nf < 4; nf++) {
                        float* c = acc[mf][g * 4 + nf];
                        mma16816(c, Ah, Bh[nf]);
                        mma16816(c, Ah, Bl[nf]);
                        mma16816(c, Al, Bh[nf]);
                    }
                }
            }
        }
        __syncthreads();
    }

    // epilogue: bias + store to h2 [b][co][pos]
#pragma unroll
    for (int mf = 0; mf < 4; mf++) {
        const int coB = coBase + mwarp * 64 + mf * 16 + (lane >> 2);
        const float bias0 = b2[coB];
        const float bias1 = b2[coB + 8];
#pragma unroll
        for (int nf = 0; nf < 8; nf++) {
#pragma unroll
            for (int i = 0; i < 4; i++) {
                const int co = coB + ((i >> 1) << 3);
                const int n  = n0 + nwarp * 64 + nf * 8 + ((lane & 3) << 1) + (i & 1);
                const int bi = n / 36;
                const int pp = n - bi * 36;
                g_h2[(size_t)bi * 9216 + co * 36 + pp] =
                    acc[mf][nf][i] + ((i >> 1) ? bias1 : bias0);
            }
        }
    }
}

// ---------------------------------------------------------------------------
// primary capsule squash (unchanged)
// ---------------------------------------------------------------------------
__global__ __launch_bounds__(256) void k_squash_pc()
{
    unsigned idx = blockIdx.x * 256u + threadIdx.x;
    if (idx >= 589824u) return;
    const float4* p = (const float4*)(g_h2 + (size_t)idx * 8);
    float4 a = p[0], b = p[1];
    float sn = a.x*a.x + a.y*a.y + a.z*a.z + a.w*a.w
             + b.x*b.x + b.y*b.y + b.z*b.z + b.w*b.w;
    float sc = sn / ((1.f + sn) * (sqrtf(sn) + 1e-6f));
    a.x *= sc; a.y *= sc; a.z *= sc; a.w *= sc;
    b.x *= sc; b.y *= sc; b.z *= sc; b.w *= sc;
    float4* q = (float4*)(g_u + (size_t)idx * 8);
    q[0] = a; q[1] = b;
}

// ---------------------------------------------------------------------------
// u_hat -> fp16. grid (288, 8), block 256.
// ---------------------------------------------------------------------------
__global__ __launch_bounds__(256) void k_uhat(const float* __restrict__ W)
{
    __shared__ float Wsm[4 * 1280];
    __shared__ float usm[64 * 32];
    const int capg = blockIdx.x * 4;
    const int img0 = blockIdx.y * 64;
    const int id   = threadIdx.x;
    {
        const float4* Wg = (const float4*)(W + (size_t)capg * 1280);
        float4* Ws4 = (float4*)Wsm;
        for (int i = id; i < 1280; i += 256) Ws4[i] = Wg[i];
        float4* us4 = (float4*)usm;
        for (int i = id; i < 512; i += 256) {
            int im = i >> 3, r = i & 7;
            us4[i] = *(const float4*)(g_u + (size_t)(img0 + im) * 9216
                                      + capg * 8 + r * 4);
        }
    }
    __syncthreads();
    for (int it = 0; it < 40; it++) {
        int flat = it * 256 + id;
        int oe4  = flat % 40;
        int cap  = (flat / 40) & 3;
        int im   = flat / 160;
        int o    = oe4 >> 2;
        int e0   = (oe4 & 3) * 4;
        const float*  up = &usm[im * 32 + cap * 8];
        const float4* Wp = (const float4*)&Wsm[cap * 1280 + o * 128 + e0];
        float4 acc = make_float4(0.f, 0.f, 0.f, 0.f);
#pragma unroll
        for (int d = 0; d < 8; d++) {
            float  ud = up[d];
            float4 w4 = Wp[d * 4];
            acc.x = fmaf(ud, w4.x, acc.x);
            acc.y = fmaf(ud, w4.y, acc.y);
            acc.z = fmaf(ud, w4.z, acc.z);
            acc.w = fmaf(ud, w4.w, acc.w);
        }
        __half2 h0 = __floats2half2_rn(acc.x, acc.y);
        __half2 h1 = __floats2half2_rn(acc.z, acc.w);
        uint2 pk = make_uint2(*(uint32_t*)&h0, *(uint32_t*)&h1);
        *(uint2*)&g_uhat_h[((size_t)(img0 + im) * 1152 + capg + cap) * 160
                           + o * 16 + e0] = pk;
    }
}

// ---------------------------------------------------------------------------
// fused routing iteration: logits + softmax + weighted reduce, ONE u_hat pass.
// grid (512, 9), block 160. chunk = 128 caps. Writes partial s to g_spart.
// uniform=1: c = 0.1 (iteration 0, no logits needed).
// ---------------------------------------------------------------------------
__global__ __launch_bounds__(160) void k_route(int uniform)
{
    __shared__ float vs[160];
    __shared__ float c_sm[128][10];
    const int b     = blockIdx.x;
    const int chunk = blockIdx.y;
    const int tid   = threadIdx.x;
    const __half* ub = g_uhat_h + (size_t)b * 184320 + (size_t)chunk * 128 * 160;

    if (!uniform) {
        vs[tid] = g_vsum[b * 160 + tid];
        __syncthreads();
        if (tid < 128) {
            const __half2* row = (const __half2*)(ub + (size_t)tid * 160);
            float t[10];
#pragma unroll
            for (int o = 0; o < 10; o++) {
                float s = 0.f;
#pragma unroll
                for (int e2 = 0; e2 < 8; e2++) {
                    float2 f = __half22float2(row[o * 8 + e2]);
                    s += f.x * vs[o * 16 + e2 * 2] + f.y * vs[o * 16 + e2 * 2 + 1];
                }
                t[o] = s;
            }
            float m = t[0];
#pragma unroll
            for (int o = 1; o < 10; o++) m = fmaxf(m, t[o]);
            float se = 0.f;
#pragma unroll
            for (int o = 0; o < 10; o++) { t[o] = expf(t[o] - m); se += t[o]; }
            float inv = 1.f / se;
#pragma unroll
            for (int o = 0; o < 10; o++) c_sm[tid][o] = t[o] * inv;
        }
        __syncthreads();
    }

    const int oe = tid;
    const int o  = oe >> 4;
    float acc = 0.f;
    if (uniform) {
#pragma unroll 4
        for (int cap = 0; cap < 128; cap++)
            acc += __half2float(ub[(size_t)cap * 160 + oe]);
        acc *= 0.1f;
    } else {
#pragma unroll 4
        for (int cap = 0; cap < 128; cap++)
            acc = fmaf(c_sm[cap][o], __half2float(ub[(size_t)cap * 160 + oe]), acc);
    }
    g_spart[((size_t)chunk * 512 + b) * 160 + oe] = acc;
}

// ---------------------------------------------------------------------------
// sum partials + squash; mode 0: vsum = v; 1: vsum += v; 2: out = v
// ---------------------------------------------------------------------------
__global__ void k_squash_v(float* __restrict__ out, int mode)
{
    int idx = blockIdx.x * 256 + threadIdx.x;
    if (idx >= 5120) return;
    float4 r[4];
#pragma unroll
    for (int i = 0; i < 4; i++) r[i] = make_float4(0.f, 0.f, 0.f, 0.f);
#pragma unroll
    for (int p = 0; p < 9; p++) {
        const float4* sp = (const float4*)(g_spart + (size_t)p * 81920
                                           + (size_t)idx * 16);
#pragma unroll
        for (int i = 0; i < 4; i++) {
            float4 v = sp[i];
            r[i].x += v.x; r[i].y += v.y; r[i].z += v.z; r[i].w += v.w;
        }
    }
    float sn = 0.f;
#pragma unroll
    for (int i = 0; i < 4; i++)
        sn += r[i].x*r[i].x + r[i].y*r[i].y + r[i].z*r[i].z + r[i].w*r[i].w;
    float sc = sn / ((1.f + sn) * (sqrtf(sn) + 1e-6f));
#pragma unroll
    for (int i = 0; i < 4; i++) {
        r[i].x *= sc; r[i].y *= sc; r[i].z *= sc; r[i].w *= sc;
    }
    if (mode == 0) {
        float4* q = (float4*)(g_vsum + (size_t)idx * 16);
#pragma unroll
        for (int i = 0; i < 4; i++) q[i] = r[i];
    } else if (mode == 1) {
        float4* q = (float4*)(g_vsum + (size_t)idx * 16);
#pragma unroll
        for (int i = 0; i < 4; i++) {
            float4 old = q[i];
            old.x += r[i].x; old.y += r[i].y; old.z += r[i].z; old.w += r[i].w;
            q[i] = old;
        }
    } else {
        float4* q = (float4*)(out + (size_t)idx * 16);
#pragma unroll
        for (int i = 0; i < 4; i++) q[i] = r[i];
    }
}

// ---------------------------------------------------------------------------
extern "C" void kernel_launch(void* const* d_in, const int* in_sizes, int n_in,
                              void* d_out, int out_size)
{
    const float* x   = (const float*)d_in[0];
    const float* w1  = (const float*)d_in[1];
    const float* b1  = (const float*)d_in[2];
    const float* w2  = (const float*)d_in[3];
    const float* b2  = (const float*)d_in[4];
    const float* W   = (const float*)d_in[5];
    float* out = (float*)d_out;

    cudaFuncSetAttribute(k_conv2mma,
                         cudaFuncAttributeMaxDynamicSharedMemorySize, 196608);

    k_conv1<<<dim3(512, 8), 256>>>(x, w1, b1);
    k_wprep<<<dim3(81, 8), 256>>>(w2);
    k_tobf16<<<dim3(512, 25), 256>>>();
    k_conv2mma<<<dim3(72, 2), 256, 196608>>>(b2);
    k_squash_pc<<<2304, 256>>>();
    k_uhat<<<dim3(288, 8), 256>>>(W);

    k_route<<<dim3(512, 9), 160>>>(1);       // iter 0: uniform c
    k_squash_v<<<20, 256>>>(nullptr, 0);     // vsum = v0
    k_route<<<dim3(512, 9), 160>>>(0);       // iter 1
    k_squash_v<<<20, 256>>>(nullptr, 1);     // vsum += v1
    k_route<<<dim3(512, 9), 160>>>(0);       // iter 2
    k_squash_v<<<20, 256>>>(out, 2);         // out = v2
}

// round 5
// speedup vs baseline: 2.4670x; 1.0321x over previous
#include <cuda_runtime.h>
#include <cuda_bf16.h>
#include <cuda_fp16.h>
#include <cstdint>
#include <math.h>

// ===========================================================================
// CapsNet forward, B=512 — Round 5:
//  * conv1 fused: fp32 conv + relu -> NHWC bf16 hi/lo direct (k_tobf16 gone)
//  * conv2mma: A-ldsm hoisted, flat B register blocking (64 ldsm.x4/chunk)
//  * k_route: smem-staged u_hat tile (kills 8x sector amplification)
//  * k_wprep: smem transpose, coalesced both sides
// ===========================================================================

// ------------------------------ scratch ------------------------------------
__device__ __nv_bfloat16  g_h1t_hi[512u * 400u * 256u];    // 105 MB NHWC
__device__ __nv_bfloat16  g_h1t_lo[512u * 400u * 256u];
__device__ __nv_bfloat16  g_w2t_hi[81u * 256u * 256u];     // 10.6 MB
__device__ __nv_bfloat16  g_w2t_lo[81u * 256u * 256u];
__device__ float  g_h2[512u * 9216u];
__device__ float  g_u [512u * 9216u];
__device__ __half g_uhat_h[512u * 1152u * 160u];           // 188.7 MB fp16
__device__ float  g_spart[9u * 512u * 160u];
__device__ float  g_vsum[512u * 160u];

// ------------------------------ PTX helpers --------------------------------
__device__ __forceinline__ uint32_t smem_u32(const void* p) {
    uint32_t a;
    asm("{ .reg .u64 t; cvta.to.shared.u64 t, %1; cvt.u32.u64 %0, t; }"
        : "=r"(a) : "l"(p));
    return a;
}
#define CP16(dst, src) \
    asm volatile("cp.async.cg.shared.global [%0], [%1], 16;" :: "r"(dst), "l"(src) : "memory")
#define CP_COMMIT() asm volatile("cp.async.commit_group;" ::: "memory")
#define CP_WAIT1()  asm volatile("cp.async.wait_group 1;" ::: "memory")
#define CP_WAIT0()  asm volatile("cp.async.wait_group 0;" ::: "memory")

__device__ __forceinline__ void ldsm_x4(uint32_t* r, uint32_t addr) {
    asm volatile("ldmatrix.sync.aligned.m8n8.x4.shared.b16 {%0,%1,%2,%3}, [%4];"
                 : "=r"(r[0]), "=r"(r[1]), "=r"(r[2]), "=r"(r[3]) : "r"(addr));
}
__device__ __forceinline__ void mma16816(float* c, const uint32_t* a,
                                         const uint32_t* b) {
    asm volatile("mma.sync.aligned.m16n8k16.row.col.f32.bf16.bf16.f32 "
                 "{%0,%1,%2,%3}, {%4,%5,%6,%7}, {%8,%9}, {%0,%1,%2,%3};"
                 : "+f"(c[0]), "+f"(c[1]), "+f"(c[2]), "+f"(c[3])
                 : "r"(a[0]), "r"(a[1]), "r"(a[2]), "r"(a[3]),
                   "r"(b[0]), "r"(b[1]));
}
__device__ __forceinline__ uint32_t swz(uint32_t o) {
    return o ^ ((o >> 3) & 0x70);
}

// ---------------------------------------------------------------------------
// conv1 + relu + bf16 hi/lo split + NHWC store. grid (512, 8), block 256,
// dynamic smem 104512 B: xs[2352]f | ws[7776]f | st_hi[400][40]h | st_lo.
// ---------------------------------------------------------------------------
__global__ __launch_bounds__(256) void k_conv1(const float* __restrict__ x,
                                               const float* __restrict__ w1,
                                               const float* __restrict__ b1)
{
    extern __shared__ __align__(16) char c1smem[];
    float* xs = (float*)c1smem;                       // 2352 f
    float* ws = xs + 2352;                            // 7776 f (ends 40512 B)
    __nv_bfloat16* st_hi = (__nv_bfloat16*)(c1smem + 40512);   // [400][40]
    __nv_bfloat16* st_lo = (__nv_bfloat16*)(c1smem + 72512);   // [400][40]

    const int b  = blockIdx.x;
    const int cg = blockIdx.y;
    const int id = threadIdx.x;
    {
        const float4* xg = (const float4*)(x + b * 2352);
        float4* xs4 = (float4*)xs;
        for (int i = id; i < 588; i += 256) xs4[i] = xg[i];
        const float4* wg = (const float4*)(w1 + cg * 7776);
        float4* ws4 = (float4*)ws;
        for (int i = id; i < 1944; i += 256) ws4[i] = wg[i];
    }
    __syncthreads();
    const int ty = id & 3;
    const int tx = id >> 2;
    float bias[8];
#pragma unroll
    for (int i = 0; i < 8; i++) bias[i] = b1[cg * 32 + ty + 4 * i];

    for (int qi = 0; qi < 2; qi++) {
        int gq = tx + 64 * qi;
        if (gq < 100) {
            int oy  = gq / 5;
            int oxb = (gq % 5) * 4;
            float acc[8][4];
#pragma unroll
            for (int i = 0; i < 8; i++)
#pragma unroll
                for (int j = 0; j < 4; j++) acc[i][j] = 0.f;
            for (int c = 0; c < 3; c++) {
                for (int ky = 0; ky < 9; ky++) {
                    const float* xrow = &xs[(c * 28 + oy + ky) * 28 + oxb];
                    float rin[12];
                    *(float4*)(rin)     = *(const float4*)(xrow);
                    *(float4*)(rin + 4) = *(const float4*)(xrow + 4);
                    *(float4*)(rin + 8) = *(const float4*)(xrow + 8);
                    const int kb = c * 81 + ky * 9;
#pragma unroll
                    for (int kx = 0; kx < 9; kx++) {
#pragma unroll
                        for (int i = 0; i < 8; i++) {
                            float w = ws[(ty + 4 * i) * 243 + kb + kx];
                            acc[i][0] = fmaf(w, rin[kx],     acc[i][0]);
                            acc[i][1] = fmaf(w, rin[kx + 1], acc[i][1]);
                            acc[i][2] = fmaf(w, rin[kx + 2], acc[i][2]);
                            acc[i][3] = fmaf(w, rin[kx + 3], acc[i][3]);
                        }
                    }
                }
            }
            // relu + split + stage:  st[pix][ch]
#pragma unroll
            for (int i = 0; i < 8; i++) {
                const int ch = ty + 4 * i;
#pragma unroll
                for (int j = 0; j < 4; j++) {
                    const int pix = gq * 4 + j;
                    float v = fmaxf(acc[i][j] + bias[i], 0.f);
                    __nv_bfloat16 h = __float2bfloat16(v);
                    st_hi[pix * 40 + ch] = h;
                    st_lo[pix * 40 + ch] = __float2bfloat16(v - __bfloat162float(h));
                }
            }
        }
    }
    __syncthreads();

    // output: [b][pix][cg*32 .. +31] hi/lo, 4 x uint4 per pix per buffer
    for (int f = id; f < 1600; f += 256) {
        const int pix = f >> 2;
        const int j   = f & 3;
        const size_t dst = ((size_t)b * 400 + pix) * 256 + cg * 32 + j * 8;
        *(uint4*)&g_h1t_hi[dst] = *(const uint4*)&st_hi[pix * 40 + j * 8];
        *(uint4*)&g_h1t_lo[dst] = *(const uint4*)&st_lo[pix * 40 + j * 8];
    }
}

// ---------------------------------------------------------------------------
// W2 [co][c][9][9] -> [kykx][co][c] bf16 hi/lo. grid 256 (one co), block 256.
// Coalesced gmem reads, smem transpose, coalesced writes.
// ---------------------------------------------------------------------------
__global__ __launch_bounds__(256) void k_wprep(const float* __restrict__ w2)
{
    __shared__ float wt[128 * 81];      // 41.5 KB: chunk of 128 c rows
    const int co  = blockIdx.x;
    const int id  = threadIdx.x;
    const int c   = id & 127;
    const int hf  = id >> 7;            // 0: kk 0..40, 1: kk 41..80

    for (int cc = 0; cc < 2; cc++) {
        __syncthreads();
        const float* src = w2 + (size_t)co * 20736 + cc * 128 * 81;
        for (int i = id; i < 128 * 81; i += 256) wt[i] = src[i];
        __syncthreads();
        const int k0 = hf ? 41 : 0;
        const int k1 = hf ? 81 : 41;
        for (int kk = k0; kk < k1; kk++) {
            float v = wt[c * 81 + kk];
            __nv_bfloat16 h = __float2bfloat16(v);
            size_t d = ((size_t)kk * 256 + co) * 256 + cc * 128 + c;
            g_w2t_hi[d] = h;
            g_w2t_lo[d] = __float2bfloat16(v - __bfloat162float(h));
        }
    }
}

// ---------------------------------------------------------------------------
// conv2 implicit GEMM via mma.sync. grid (72, 2), block 256, 196608 B smem.
// CTA tile M=128 x N=256; 324 K64 chunks; warp tile 64x64 (2M x 4N warps).
// Per q: 8 B-ldsm.x4 (flat 8 frags hi+lo), per mf 2 A-ldsm.x4 + 24 mma.
// ---------------------------------------------------------------------------
#define STAGE_BYTES 98304
#define AH_OFF 0
#define AL_OFF 16384
#define BH_OFF 32768
#define BL_OFF 65536
#define NCHUNK 324

__device__ __forceinline__ void load_chunk(
    uint32_t stbase, int kk, int c0, int tid, int arow,
    const __nv_bfloat16* wsrc, uint32_t adst_off,
    int bimg, int oy, int ox, int coBase)
{
    const int ky = kk / 9, kx = kk - ky * 9;
    const __nv_bfloat16* aS =
        wsrc + ((size_t)kk * 256 + coBase + arow) * 256 + c0;
    const size_t pix = (size_t)bimg * 400 + (2 * oy + ky) * 20 + (2 * ox + kx);
    const __nv_bfloat16* bSh = g_h1t_hi + pix * 256 + c0;
    const __nv_bfloat16* bSl = g_h1t_lo + pix * 256 + c0;
    const uint32_t aD  = stbase + adst_off;
    const uint32_t bDh = stbase + BH_OFF;
    const uint32_t bDl = stbase + BL_OFF;
#pragma unroll
    for (int u = 0; u < 8; u++) {
        uint32_t oa = swz(arow * 128 + u * 16);
        CP16(aD + oa, aS + u * 8);
        uint32_t ob = swz(tid * 128 + u * 16);
        CP16(bDh + ob, bSh + u * 8);
        CP16(bDl + ob, bSl + u * 8);
    }
}

__global__ __launch_bounds__(256) void k_conv2mma(const float* __restrict__ b2)
{
    extern __shared__ __align__(1024) char dynsmem[];
    const uint32_t sb = smem_u32(dynsmem);
    const int tid  = threadIdx.x;
    const int warp = tid >> 5;
    const int lane = tid & 31;
    const int n0     = blockIdx.x * 256;
    const int coBase = blockIdx.y * 128;
    const int mwarp = warp & 1;
    const int nwarp = warp >> 1;

    const int arow = tid & 127;
    const __nv_bfloat16* wsrc = (tid < 128) ? g_w2t_hi : g_w2t_lo;
    const uint32_t adst_off   = (tid < 128) ? AH_OFF : AL_OFF;
    const int nB   = n0 + tid;
    const int bimg = nB / 36;
    const int pos  = nB - bimg * 36;
    const int oy   = pos / 6, ox = pos - oy * 6;

    // ldmatrix lane addressing
    const int aRowSub = lane & 15;
    const int aColSel = (lane >> 4) * 16;
    const int bMat    = lane >> 3;
    const int bSub    = lane & 7;
    const int bNfSel  = bMat >> 1;
    const int bKSel   = (bMat & 1) * 16;

    float acc[4][8][4];
#pragma unroll
    for (int mf = 0; mf < 4; mf++)
#pragma unroll
        for (int nf = 0; nf < 8; nf++)
#pragma unroll
            for (int i = 0; i < 4; i++) acc[mf][nf][i] = 0.f;

    load_chunk(sb, 0, 0, tid, arow, wsrc, adst_off, bimg, oy, ox, coBase);
    CP_COMMIT();

    for (int t = 0; t < NCHUNK; t++) {
        const int s = t & 1, s2 = s ^ 1;
        if (t + 1 < NCHUNK) {
            const int tn = t + 1;
            load_chunk(sb + s2 * STAGE_BYTES, tn >> 2, (tn & 3) * 64,
                       tid, arow, wsrc, adst_off, bimg, oy, ox, coBase);
            CP_COMMIT();
            CP_WAIT1();
        } else {
            CP_WAIT0();
        }
        __syncthreads();

        const uint32_t stb = sb + s * STAGE_BYTES;
        const uint32_t ah = stb + AH_OFF, al = stb + AL_OFF;
        const uint32_t bh = stb + BH_OFF, bl = stb + BL_OFF;

#pragma unroll
        for (int q = 0; q < 4; q++) {
            const int qb = q * 32;
            // flat B fragments: 8 per dtype
            uint32_t Bh[8][2], Bl[8][2];
#pragma unroll
            for (int gp = 0; gp < 4; gp++) {
                uint32_t off = swz((nwarp * 64 + (gp * 2 + bNfSel) * 8 + bSub) * 128
                                   + qb + bKSel);
                uint32_t r[4];
                ldsm_x4(r, bh + off);
                Bh[gp*2][0] = r[0]; Bh[gp*2][1] = r[1];
                Bh[gp*2+1][0] = r[2]; Bh[gp*2+1][1] = r[3];
                ldsm_x4(r, bl + off);
                Bl[gp*2][0] = r[0]; Bl[gp*2][1] = r[1];
                Bl[gp*2+1][0] = r[2]; Bl[gp*2+1][1] = r[3];
            }
#pragma unroll
            for (int mf = 0; mf < 4; mf++) {
                uint32_t Ah[4], Al[4];
                uint32_t offA = swz((mwarp * 64 + mf * 16 + aRowSub) * 128
                                    + qb + aColSel);
                ldsm_x4(Ah, ah + offA);
                ldsm_x4(Al, al + offA);
#pragma unroll
                for (int nf = 0; nf < 8; nf++) {
                    float* c = acc[mf][nf];
                    mma16816(c, Ah, Bh[nf]);
                    mma16816(c, Ah, Bl[nf]);
                    mma16816(c, Al, Bh[nf]);
                }
            }
        }
        __syncthreads();
    }

    // epilogue: bias + store to h2 [b][co][pos]
#pragma unroll
    for (int mf = 0; mf < 4; mf++) {
        const int coB = coBase + mwarp * 64 + mf * 16 + (lane >> 2);
        const float bias0 = b2[coB];
        const float bias1 = b2[coB + 8];
#pragma unroll
        for (int nf = 0; nf < 8; nf++) {
#pragma unroll
            for (int i = 0; i < 4; i++) {
                const int co = coB + ((i >> 1) << 3);
                const int n  = n0 + nwarp * 64 + nf * 8 + ((lane & 3) << 1) + (i & 1);
                const int bi = n / 36;
                const int pp = n - bi * 36;
                g_h2[(size_t)bi * 9216 + co * 36 + pp] =
                    acc[mf][nf][i] + ((i >> 1) ? bias1 : bias0);
            }
        }
    }
}

// ---------------------------------------------------------------------------
// primary capsule squash (unchanged)
// ---------------------------------------------------------------------------
__global__ __launch_bounds__(256) void k_squash_pc()
{
    unsigned idx = blockIdx.x * 256u + threadIdx.x;
    if (idx >= 589824u) return;
    const float4* p = (const float4*)(g_h2 + (size_t)idx * 8);
    float4 a = p[0], b = p[1];
    float sn = a.x*a.x + a.y*a.y + a.z*a.z + a.w*a.w
             + b.x*b.x + b.y*b.y + b.z*b.z + b.w*b.w;
    float sc = sn / ((1.f + sn) * (sqrtf(sn) + 1e-6f));
    a.x *= sc; a.y *= sc; a.z *= sc; a.w *= sc;
    b.x *= sc; b.y *= sc; b.z *= sc; b.w *= sc;
    float4* q = (float4*)(g_u + (size_t)idx * 8);
    q[0] = a; q[1] = b;
}

// ---------------------------------------------------------------------------
// u_hat -> fp16 (unchanged)
// ---------------------------------------------------------------------------
__global__ __launch_bounds__(256) void k_uhat(const float* __restrict__ W)
{
    __shared__ float Wsm[4 * 1280];
    __shared__ float usm[64 * 32];
    const int capg = blockIdx.x * 4;
    const int img0 = blockIdx.y * 64;
    const int id   = threadIdx.x;
    {
        const float4* Wg = (const float4*)(W + (size_t)capg * 1280);
        float4* Ws4 = (float4*)Wsm;
        for (int i = id; i < 1280; i += 256) Ws4[i] = Wg[i];
        float4* us4 = (float4*)usm;
        for (int i = id; i < 512; i += 256) {
            int im = i >> 3, r = i & 7;
            us4[i] = *(const float4*)(g_u + (size_t)(img0 + im) * 9216
                                      + capg * 8 + r * 4);
        }
    }
    __syncthreads();
    for (int it = 0; it < 40; it++) {
        int flat = it * 256 + id;
        int oe4  = flat % 40;
        int cap  = (flat / 40) & 3;
        int im   = flat / 160;
        int o    = oe4 >> 2;
        int e0   = (oe4 & 3) * 4;
        const float*  up = &usm[im * 32 + cap * 8];
        const float4* Wp = (const float4*)&Wsm[cap * 1280 + o * 128 + e0];
        float4 acc = make_float4(0.f, 0.f, 0.f, 0.f);
#pragma unroll
        for (int d = 0; d < 8; d++) {
            float  ud = up[d];
            float4 w4 = Wp[d * 4];
            acc.x = fmaf(ud, w4.x, acc.x);
            acc.y = fmaf(ud, w4.y, acc.y);
            acc.z = fmaf(ud, w4.z, acc.z);
            acc.w = fmaf(ud, w4.w, acc.w);
        }
        __half2 h0 = __floats2half2_rn(acc.x, acc.y);
        __half2 h1 = __floats2half2_rn(acc.z, acc.w);
        uint2 pk = make_uint2(*(uint32_t*)&h0, *(uint32_t*)&h1);
        *(uint2*)&g_uhat_h[((size_t)(img0 + im) * 1152 + capg + cap) * 160
                           + o * 16 + e0] = pk;
    }
}

// ---------------------------------------------------------------------------
// fused routing iteration, smem-staged. grid (512, 9), block 160.
// ---------------------------------------------------------------------------
__global__ __launch_bounds__(160) void k_route(int uniform)
{
    __shared__ __align__(16) __half tile[128 * 168];   // padded rows (336 B)
    __shared__ float vs[160];
    __shared__ float c_sm[128][10];
    const int b     = blockIdx.x;
    const int chunk = blockIdx.y;
    const int tid   = threadIdx.x;
    const __half* ub = g_uhat_h + (size_t)b * 184320 + (size_t)chunk * 128 * 160;

    if (uniform) {
        // single coalesced column pass over gmem
        const int oe = tid;
        float acc = 0.f;
#pragma unroll 4
        for (int cap = 0; cap < 128; cap++)
            acc += __half2float(ub[(size_t)cap * 160 + oe]);
        g_spart[((size_t)chunk * 512 + b) * 160 + oe] = acc * 0.1f;
        return;
    }

    // stage tile coalesced: 128 rows x 160 halfs (20 uint4 per row)
    vs[tid] = g_vsum[b * 160 + tid];
    for (int f = tid; f < 2560; f += 160) {
        const int r = f / 20, j = f % 20;
        *(uint4*)&tile[r * 168 + j * 8] = *(const uint4*)(ub + (size_t)r * 160 + j * 8);
    }
    __syncthreads();

    if (tid < 128) {
        const __half2* row = (const __half2*)&tile[tid * 168];
        float t[10];
#pragma unroll
        for (int o = 0; o < 10; o++) {
            float s = 0.f;
#pragma unroll
            for (int e2 = 0; e2 < 8; e2++) {
                float2 f = __half22float2(row[o * 8 + e2]);
                s += f.x * vs[o * 16 + e2 * 2] + f.y * vs[o * 16 + e2 * 2 + 1];
            }
            t[o] = s;
        }
        float m = t[0];
#pragma unroll
        for (int o = 1; o < 10; o++) m = fmaxf(m, t[o]);
        float se = 0.f;
#pragma unroll
        for (int o = 0; o < 10; o++) { t[o] = expf(t[o] - m); se += t[o]; }
        float inv = 1.f / se;
#pragma unroll
        for (int o = 0; o < 10; o++) c_sm[tid][o] = t[o] * inv;
    }
    __syncthreads();

    const int oe = tid;
    const int o  = oe >> 4;
    float acc = 0.f;
#pragma unroll 4
    for (int cap = 0; cap < 128; cap++)
        acc = fmaf(c_sm[cap][o], __half2float(tile[cap * 168 + oe]), acc);
    g_spart[((size_t)chunk * 512 + b) * 160 + oe] = acc;
}

// ---------------------------------------------------------------------------
// sum partials + squash; mode 0: vsum = v; 1: vsum += v; 2: out = v
// ---------------------------------------------------------------------------
__global__ void k_squash_v(float* __restrict__ out, int mode)
{
    int idx = blockIdx.x * 256 + threadIdx.x;
    if (idx >= 5120) return;
    float4 r[4];
#pragma unroll
    for (int i = 0; i < 4; i++) r[i] = make_float4(0.f, 0.f, 0.f, 0.f);
#pragma unroll
    for (int p = 0; p < 9; p++) {
        const float4* sp = (const float4*)(g_spart + (size_t)p * 81920
                                           + (size_t)idx * 16);
#pragma unroll
        for (int i = 0; i < 4; i++) {
            float4 v = sp[i];
            r[i].x += v.x; r[i].y += v.y; r[i].z += v.z; r[i].w += v.w;
        }
    }
    float sn = 0.f;
#pragma unroll
    for (int i = 0; i < 4; i++)
        sn += r[i].x*r[i].x + r[i].y*r[i].y + r[i].z*r[i].z + r[i].w*r[i].w;
    float sc = sn / ((1.f + sn) * (sqrtf(sn) + 1e-6f));
#pragma unroll
    for (int i = 0; i < 4; i++) {
        r[i].x *= sc; r[i].y *= sc; r[i].z *= sc; r[i].w *= sc;
    }
    if (mode == 0) {
        float4* q = (float4*)(g_vsum + (size_t)idx * 16);
#pragma unroll
        for (int i = 0; i < 4; i++) q[i] = r[i];
    } else if (mode == 1) {
        float4* q = (float4*)(g_vsum + (size_t)idx * 16);
#pragma unroll
        for (int i = 0; i < 4; i++) {
            float4 old = q[i];
            old.x += r[i].x; old.y += r[i].y; old.z += r[i].z; old.w += r[i].w;
            q[i] = old;
        }
    } else {
        float4* q = (float4*)(out + (size_t)idx * 16);
#pragma unroll
        for (int i = 0; i < 4; i++) q[i] = r[i];
    }
}

// ---------------------------------------------------------------------------
extern "C" void kernel_launch(void* const* d_in, const int* in_sizes, int n_in,
                              void* d_out, int out_size)
{
    const float* x   = (const float*)d_in[0];
    const float* w1  = (const float*)d_in[1];
    const float* b1  = (const float*)d_in[2];
    const float* w2  = (const float*)d_in[3];
    const float* b2  = (const float*)d_in[4];
    const float* W   = (const float*)d_in[5];
    float* out = (float*)d_out;

    cudaFuncSetAttribute(k_conv1,
                         cudaFuncAttributeMaxDynamicSharedMemorySize, 104512);
    cudaFuncSetAttribute(k_conv2mma,
                         cudaFuncAttributeMaxDynamicSharedMemorySize, 196608);

    k_conv1<<<dim3(512, 8), 256, 104512>>>(x, w1, b1);
    k_wprep<<<256, 256>>>(w2);
    k_conv2mma<<<dim3(72, 2), 256, 196608>>>(b2);
    k_squash_pc<<<2304, 256>>>();
    k_uhat<<<dim3(288, 8), 256>>>(W);

    k_route<<<dim3(512, 9), 160>>>(1);       // iter 0: uniform c
    k_squash_v<<<20, 256>>>(nullptr, 0);     // vsum = v0
    k_route<<<dim3(512, 9), 160>>>(0);       // iter 1
    k_squash_v<<<20, 256>>>(nullptr, 1);     // vsum += v1
    k_route<<<dim3(512, 9), 160>>>(0);       // iter 2
    k_squash_v<<<20, 256>>>(out, 2);         // out = v2
}

// round 6
// speedup vs baseline: 3.1348x; 1.2707x over previous
#include <cuda_runtime.h>
#include <cuda_bf16.h>
#include <cuda_fp16.h>
#include <cstdint>
#include <math.h>

// ===========================================================================
// CapsNet forward, B=512 — Round 6:
//  * conv2mma: 512 threads (16 warps, warp tile 32x64, 4 warps/SMSP) and
//    2-term fp16 split (A = w hi+lo exact, B = activations single fp16).
//    Stage 64KB (Ah16|Al16|B32), double buffered = 128KB.
//  * conv1 writes single fp16 NHWC h1t (no lo buffer).
//  * routing/u_hat unchanged from Round 5.
// ===========================================================================

// ------------------------------ scratch ------------------------------------
__device__ __half g_h1t   [512u * 400u * 256u];            // 105 MB NHWC fp16
__device__ __half g_w2t_hi[81u * 256u * 256u];             // 10.6 MB
__device__ __half g_w2t_lo[81u * 256u * 256u];
__device__ float  g_h2[512u * 9216u];
__device__ float  g_u [512u * 9216u];
__device__ __half g_uhat_h[512u * 1152u * 160u];           // 188.7 MB fp16
__device__ float  g_spart[9u * 512u * 160u];
__device__ float  g_vsum[512u * 160u];

// ------------------------------ PTX helpers --------------------------------
__device__ __forceinline__ uint32_t smem_u32(const void* p) {
    uint32_t a;
    asm("{ .reg .u64 t; cvta.to.shared.u64 t, %1; cvt.u32.u64 %0, t; }"
        : "=r"(a) : "l"(p));
    return a;
}
#define CP16(dst, src) \
    asm volatile("cp.async.cg.shared.global [%0], [%1], 16;" :: "r"(dst), "l"(src) : "memory")
#define CP_COMMIT() asm volatile("cp.async.commit_group;" ::: "memory")
#define CP_WAIT1()  asm volatile("cp.async.wait_group 1;" ::: "memory")
#define CP_WAIT0()  asm volatile("cp.async.wait_group 0;" ::: "memory")

__device__ __forceinline__ void ldsm_x4(uint32_t* r, uint32_t addr) {
    asm volatile("ldmatrix.sync.aligned.m8n8.x4.shared.b16 {%0,%1,%2,%3}, [%4];"
                 : "=r"(r[0]), "=r"(r[1]), "=r"(r[2]), "=r"(r[3]) : "r"(addr));
}
__device__ __forceinline__ void mma16816h(float* c, const uint32_t* a,
                                          const uint32_t* b) {
    asm volatile("mma.sync.aligned.m16n8k16.row.col.f32.f16.f16.f32 "
                 "{%0,%1,%2,%3}, {%4,%5,%6,%7}, {%8,%9}, {%0,%1,%2,%3};"
                 : "+f"(c[0]), "+f"(c[1]), "+f"(c[2]), "+f"(c[3])
                 : "r"(a[0]), "r"(a[1]), "r"(a[2]), "r"(a[3]),
                   "r"(b[0]), "r"(b[1]));
}
__device__ __forceinline__ uint32_t swz(uint32_t o) {
    return o ^ ((o >> 3) & 0x70);
}

// ---------------------------------------------------------------------------
// conv1 + relu -> single fp16 NHWC. grid (512, 8), block 256,
// dyn smem 72512 B: xs[2352]f | ws[7776]f | st[400][40]h.
// ---------------------------------------------------------------------------
__global__ __launch_bounds__(256) void k_conv1(const float* __restrict__ x,
                                               const float* __restrict__ w1,
                                               const float* __restrict__ b1)
{
    extern __shared__ __align__(16) char c1smem[];
    float* xs = (float*)c1smem;                       // 2352 f
    float* ws = xs + 2352;                            // 7776 f (ends 40512 B)
    __half* st = (__half*)(c1smem + 40512);           // [400][40]

    const int b  = blockIdx.x;
    const int cg = blockIdx.y;
    const int id = threadIdx.x;
    {
        const float4* xg = (const float4*)(x + b * 2352);
        float4* xs4 = (float4*)xs;
        for (int i = id; i < 588; i += 256) xs4[i] = xg[i];
        const float4* wg = (const float4*)(w1 + cg * 7776);
        float4* ws4 = (float4*)ws;
        for (int i = id; i < 1944; i += 256) ws4[i] = wg[i];
    }
    __syncthreads();
    const int ty = id & 3;
    const int tx = id >> 2;
    float bias[8];
#pragma unroll
    for (int i = 0; i < 8; i++) bias[i] = b1[cg * 32 + ty + 4 * i];

    for (int qi = 0; qi < 2; qi++) {
        int gq = tx + 64 * qi;
        if (gq < 100) {
            int oy  = gq / 5;
            int oxb = (gq % 5) * 4;
            float acc[8][4];
#pragma unroll
            for (int i = 0; i < 8; i++)
#pragma unroll
                for (int j = 0; j < 4; j++) acc[i][j] = 0.f;
            for (int c = 0; c < 3; c++) {
                for (int ky = 0; ky < 9; ky++) {
                    const float* xrow = &xs[(c * 28 + oy + ky) * 28 + oxb];
                    float rin[12];
                    *(float4*)(rin)     = *(const float4*)(xrow);
                    *(float4*)(rin + 4) = *(const float4*)(xrow + 4);
                    *(float4*)(rin + 8) = *(const float4*)(xrow + 8);
                    const int kb = c * 81 + ky * 9;
#pragma unroll
                    for (int kx = 0; kx < 9; kx++) {
#pragma unroll
                        for (int i = 0; i < 8; i++) {
                            float w = ws[(ty + 4 * i) * 243 + kb + kx];
                            acc[i][0] = fmaf(w, rin[kx],     acc[i][0]);
                            acc[i][1] = fmaf(w, rin[kx + 1], acc[i][1]);
                            acc[i][2] = fmaf(w, rin[kx + 2], acc[i][2]);
                            acc[i][3] = fmaf(w, rin[kx + 3], acc[i][3]);
                        }
                    }
                }
            }
#pragma unroll
            for (int i = 0; i < 8; i++) {
                const int ch = ty + 4 * i;
#pragma unroll
                for (int j = 0; j < 4; j++) {
                    const int pix = gq * 4 + j;
                    st[pix * 40 + ch] =
                        __float2half(fmaxf(acc[i][j] + bias[i], 0.f));
                }
            }
        }
    }
    __syncthreads();

    for (int f = id; f < 1600; f += 256) {
        const int pix = f >> 2;
        const int j   = f & 3;
        const size_t dst = ((size_t)b * 400 + pix) * 256 + cg * 32 + j * 8;
        *(uint4*)&g_h1t[dst] = *(const uint4*)&st[pix * 40 + j * 8];
    }
}

// ---------------------------------------------------------------------------
// W2 [co][c][9][9] -> [kykx][co][c] fp16 hi/lo. grid 256, block 256.
// ---------------------------------------------------------------------------
__global__ __launch_bounds__(256) void k_wprep(const float* __restrict__ w2)
{
    __shared__ float wt[128 * 81];
    const int co  = blockIdx.x;
    const int id  = threadIdx.x;
    const int c   = id & 127;
    const int hf  = id >> 7;

    for (int cc = 0; cc < 2; cc++) {
        __syncthreads();
        const float* src = w2 + (size_t)co * 20736 + cc * 128 * 81;
        for (int i = id; i < 128 * 81; i += 256) wt[i] = src[i];
        __syncthreads();
        const int k0 = hf ? 41 : 0;
        const int k1 = hf ? 81 : 41;
        for (int kk = k0; kk < k1; kk++) {
            float v = wt[c * 81 + kk];
            __half h = __float2half(v);
            size_t d = ((size_t)kk * 256 + co) * 256 + cc * 128 + c;
            g_w2t_hi[d] = h;
            g_w2t_lo[d] = __float2half(v - __half2float(h));
        }
    }
}

// ---------------------------------------------------------------------------
// conv2 implicit GEMM via mma.sync, 512 threads. grid (72, 2), 131072 B smem.
// CTA tile M=128 x N=256; 324 K64 chunks; warps 4(M) x 4(N), warp tile 32x64.
// Terms per chunk: Ah*B + Al*B (fp16).
// Stage 65536 B: Ah[16K] Al[16K] B[32K]; 2 stages.
// ---------------------------------------------------------------------------
#define STAGE_BYTES 65536
#define AH_OFF 0
#define AL_OFF 16384
#define B_OFF  32768
#define NCHUNK 324

__device__ __forceinline__ void load_chunk(
    uint32_t stbase, int kk, int c0, int tid,
    int bimg, int oy, int ox, int coBase)
{
    const int ky = kk / 9, kx = kk - ky * 9;
    if (tid < 256) {
        const size_t pix = (size_t)bimg * 400 + (2 * oy + ky) * 20 + (2 * ox + kx);
        const __half* src = g_h1t + pix * 256 + c0;
        const uint32_t dst = stbase + B_OFF;
#pragma unroll
        for (int u = 0; u < 8; u++) {
            uint32_t ob = swz(tid * 128 + u * 16);
            CP16(dst + ob, src + u * 8);
        }
    } else {
        const int r   = tid - 256;
        const int row = r & 127;
        const __half* base = (r < 128) ? g_w2t_hi : g_w2t_lo;
        const __half* src  = base + ((size_t)kk * 256 + coBase + row) * 256 + c0;
        const uint32_t dst = stbase + ((r < 128) ? AH_OFF : AL_OFF);
#pragma unroll
        for (int u = 0; u < 8; u++) {
            uint32_t oa = swz(row * 128 + u * 16);
            CP16(dst + oa, src + u * 8);
        }
    }
}

__global__ __launch_bounds__(512) void k_conv2mma(const float* __restrict__ b2)
{
    extern __shared__ __align__(1024) char dynsmem[];
    const uint32_t sb = smem_u32(dynsmem);
    const int tid  = threadIdx.x;
    const int warp = tid >> 5;
    const int lane = tid & 31;
    const int n0     = blockIdx.x * 256;
    const int coBase = blockIdx.y * 128;
    const int mwarp = warp & 3;       // co: mwarp*32
    const int nwarp = warp >> 2;      // n : nwarp*64

    // loader role (threads 0..255 load B row tid; 256..511 load A hi/lo)
    const int nB   = n0 + (tid & 255);
    const int bimg = nB / 36;
    const int pos  = nB - bimg * 36;
    const int oy   = pos / 6, ox = pos - oy * 6;

    // ldmatrix lane addressing
    const int aRowSub = lane & 15;
    const int aColSel = (lane >> 4) * 16;
    const int bMat    = lane >> 3;
    const int bSub    = lane & 7;
    const int bNfSel  = bMat >> 1;
    const int bKSel   = (bMat & 1) * 16;

    float acc[2][8][4];
#pragma unroll
    for (int mf = 0; mf < 2; mf++)
#pragma unroll
        for (int nf = 0; nf < 8; nf++)
#pragma unroll
            for (int i = 0; i < 4; i++) acc[mf][nf][i] = 0.f;

    load_chunk(sb, 0, 0, tid, bimg, oy, ox, coBase);
    CP_COMMIT();

    for (int t = 0; t < NCHUNK; t++) {
        const int s = t & 1, s2 = s ^ 1;
        if (t + 1 < NCHUNK) {
            const int tn = t + 1;
            load_chunk(sb + s2 * STAGE_BYTES, tn >> 2, (tn & 3) * 64,
                       tid, bimg, oy, ox, coBase);
            CP_COMMIT();
            CP_WAIT1();
        } else {
            CP_WAIT0();
        }
        __syncthreads();

        const uint32_t stb = sb + s * STAGE_BYTES;
        const uint32_t ah = stb + AH_OFF, al = stb + AL_OFF;
        const uint32_t bb = stb + B_OFF;

#pragma unroll
        for (int q = 0; q < 4; q++) {
            const int qb = q * 32;
            uint32_t B[8][2];
#pragma unroll
            for (int gp = 0; gp < 4; gp++) {
                uint32_t off = swz((nwarp * 64 + (gp * 2 + bNfSel) * 8 + bSub) * 128
                                   + qb + bKSel);
                uint32_t r[4];
                ldsm_x4(r, bb + off);
                B[gp*2][0] = r[0]; B[gp*2][1] = r[1];
                B[gp*2+1][0] = r[2]; B[gp*2+1][1] = r[3];
            }
#pragma unroll
            for (int mf = 0; mf < 2; mf++) {
                uint32_t Ah[4], Al[4];
                uint32_t offA = swz((mwarp * 32 + mf * 16 + aRowSub) * 128
                                    + qb + aColSel);
                ldsm_x4(Ah, ah + offA);
                ldsm_x4(Al, al + offA);
#pragma unroll
                for (int nf = 0; nf < 8; nf++) {
                    float* c = acc[mf][nf];
                    mma16816h(c, Ah, B[nf]);
                    mma16816h(c, Al, B[nf]);
                }
            }
        }
        __syncthreads();
    }

    // epilogue: bias + store to h2 [b][co][pos]
#pragma unroll
    for (int mf = 0; mf < 2; mf++) {
        const int coB = coBase + mwarp * 32 + mf * 16 + (lane >> 2);
        const float bias0 = b2[coB];
        const float bias1 = b2[coB + 8];
#pragma unroll
        for (int nf = 0; nf < 8; nf++) {
#pragma unroll
            for (int i = 0; i < 4; i++) {
                const int co = coB + ((i >> 1) << 3);
                const int n  = n0 + nwarp * 64 + nf * 8 + ((lane & 3) << 1) + (i & 1);
                const int bi = n / 36;
                const int pp = n - bi * 36;
                g_h2[(size_t)bi * 9216 + co * 36 + pp] =
                    acc[mf][nf][i] + ((i >> 1) ? bias1 : bias0);
            }
        }
    }
}

// ---------------------------------------------------------------------------
// primary capsule squash (unchanged)
// ---------------------------------------------------------------------------
__global__ __launch_bounds__(256) void k_squash_pc()
{
    unsigned idx = blockIdx.x * 256u + threadIdx.x;
    if (idx >= 589824u) return;
    const float4* p = (const float4*)(g_h2 + (size_t)idx * 8);
    float4 a = p[0], b = p[1];
    float sn = a.x*a.x + a.y*a.y + a.z*a.z + a.w*a.w
             + b.x*b.x + b.y*b.y + b.z*b.z + b.w*b.w;
    float sc = sn / ((1.f + sn) * (sqrtf(sn) + 1e-6f));
    a.x *= sc; a.y *= sc; a.z *= sc; a.w *= sc;
    b.x *= sc; b.y *= sc; b.z *= sc; b.w *= sc;
    float4* q = (float4*)(g_u + (size_t)idx * 8);
    q[0] = a; q[1] = b;
}

// ---------------------------------------------------------------------------
// u_hat -> fp16 (unchanged)
// ---------------------------------------------------------------------------
__global__ __launch_bounds__(256) void k_uhat(const float* __restrict__ W)
{
    __shared__ float Wsm[4 * 1280];
    __shared__ float usm[64 * 32];
    const int capg = blockIdx.x * 4;
    const int img0 = blockIdx.y * 64;
    const int id   = threadIdx.x;
    {
        const float4* Wg = (const float4*)(W + (size_t)capg * 1280);
        float4* Ws4 = (float4*)Wsm;
        for (int i = id; i < 1280; i += 256) Ws4[i] = Wg[i];
        float4* us4 = (float4*)usm;
        for (int i = id; i < 512; i += 256) {
            int im = i >> 3, r = i & 7;
            us4[i] = *(const float4*)(g_u + (size_t)(img0 + im) * 9216
                                      + capg * 8 + r * 4);
        }
    }
    __syncthreads();
    for (int it = 0; it < 40; it++) {
        int flat = it * 256 + id;
        int oe4  = flat % 40;
        int cap  = (flat / 40) & 3;
        int im   = flat / 160;
        int o    = oe4 >> 2;
        int e0   = (oe4 & 3) * 4;
        const float*  up = &usm[im * 32 + cap * 8];
        const float4* Wp = (const float4*)&Wsm[cap * 1280 + o * 128 + e0];
        float4 acc = make_float4(0.f, 0.f, 0.f, 0.f);
#pragma unroll
        for (int d = 0; d < 8; d++) {
            float  ud = up[d];
            float4 w4 = Wp[d * 4];
            acc.x = fmaf(ud, w4.x, acc.x);
            acc.y = fmaf(ud, w4.y, acc.y);
            acc.z = fmaf(ud, w4.z, acc.z);
            acc.w = fmaf(ud, w4.w, acc.w);
        }
        __half2 h0 = __floats2half2_rn(acc.x, acc.y);
        __half2 h1 = __floats2half2_rn(acc.z, acc.w);
        uint2 pk = make_uint2(*(uint32_t*)&h0, *(uint32_t*)&h1);
        *(uint2*)&g_uhat_h[((size_t)(img0 + im) * 1152 + capg + cap) * 160
                           + o * 16 + e0] = pk;
    }
}

// ---------------------------------------------------------------------------
// fused routing iteration, smem-staged (unchanged)
// ---------------------------------------------------------------------------
__global__ __launch_bounds__(160) void k_route(int uniform)
{
    __shared__ __align__(16) __half tile[128 * 168];
    __shared__ float vs[160];
    __shared__ float c_sm[128][10];
    const int b     = blockIdx.x;
    const int chunk = blockIdx.y;
    const int tid   = threadIdx.x;
    const __half* ub = g_uhat_h + (size_t)b * 184320 + (size_t)chunk * 128 * 160;

    if (uniform) {
        const int oe = tid;
        float acc = 0.f;
#pragma unroll 4
        for (int cap = 0; cap < 128; cap++)
            acc += __half2float(ub[(size_t)cap * 160 + oe]);
        g_spart[((size_t)chunk * 512 + b) * 160 + oe] = acc * 0.1f;
        return;
    }

    vs[tid] = g_vsum[b * 160 + tid];
    for (int f = tid; f < 2560; f += 160) {
        const int r = f / 20, j = f % 20;
        *(uint4*)&tile[r * 168 + j * 8] = *(const uint4*)(ub + (size_t)r * 160 + j * 8);
    }
    __syncthreads();

    if (tid < 128) {
        const __half2* row = (const __half2*)&tile[tid * 168];
        float t[10];
#pragma unroll
        for (int o = 0; o < 10; o++) {
            float s = 0.f;
#pragma unroll
            for (int e2 = 0; e2 < 8; e2++) {
                float2 f = __half22float2(row[o * 8 + e2]);
                s += f.x * vs[o * 16 + e2 * 2] + f.y * vs[o * 16 + e2 * 2 + 1];
            }
            t[o] = s;
        }
        float m = t[0];
#pragma unroll
        for (int o = 1; o < 10; o++) m = fmaxf(m, t[o]);
        float se = 0.f;
#pragma unroll
        for (int o = 0; o < 10; o++) { t[o] = expf(t[o] - m); se += t[o]; }
        float inv = 1.f / se;
#pragma unroll
        for (int o = 0; o < 10; o++) c_sm[tid][o] = t[o] * inv;
    }
    __syncthreads();

    const int oe = tid;
    const int o  = oe >> 4;
    float acc = 0.f;
#pragma unroll 4
    for (int cap = 0; cap < 128; cap++)
        acc = fmaf(c_sm[cap][o], __half2float(tile[cap * 168 + oe]), acc);
    g_spart[((size_t)chunk * 512 + b) * 160 + oe] = acc;
}

// ---------------------------------------------------------------------------
// sum partials + squash (unchanged)
// ---------------------------------------------------------------------------
__global__ void k_squash_v(float* __restrict__ out, int mode)
{
    int idx = blockIdx.x * 256 + threadIdx.x;
    if (idx >= 5120) return;
    float4 r[4];
#pragma unroll
    for (int i = 0; i < 4; i++) r[i] = make_float4(0.f, 0.f, 0.f, 0.f);
#pragma unroll
    for (int p = 0; p < 9; p++) {
        const float4* sp = (const float4*)(g_spart + (size_t)p * 81920
                                           + (size_t)idx * 16);
#pragma unroll
        for (int i = 0; i < 4; i++) {
            float4 v = sp[i];
            r[i].x += v.x; r[i].y += v.y; r[i].z += v.z; r[i].w += v.w;
        }
    }
    float sn = 0.f;
#pragma unroll
    for (int i = 0; i < 4; i++)
        sn += r[i].x*r[i].x + r[i].y*r[i].y + r[i].z*r[i].z + r[i].w*r[i].w;
    float sc = sn / ((1.f + sn) * (sqrtf(sn) + 1e-6f));
#pragma unroll
    for (int i = 0; i < 4; i++) {
        r[i].x *= sc; r[i].y *= sc; r[i].z *= sc; r[i].w *= sc;
    }
    if (mode == 0) {
        float4* q = (float4*)(g_vsum + (size_t)idx * 16);
#pragma unroll
        for (int i = 0; i < 4; i++) q[i] = r[i];
    } else if (mode == 1) {
        float4* q = (float4*)(g_vsum + (size_t)idx * 16);
#pragma unroll
        for (int i = 0; i < 4; i++) {
            float4 old = q[i];
            old.x += r[i].x; old.y += r[i].y; old.z += r[i].z; old.w += r[i].w;
            q[i] = old;
        }
    } else {
        float4* q = (float4*)(out + (size_t)idx * 16);
#pragma unroll
        for (int i = 0; i < 4; i++) q[i] = r[i];
    }
}

// ---------------------------------------------------------------------------
extern "C" void kernel_launch(void* const* d_in, const int* in_sizes, int n_in,
                              void* d_out, int out_size)
{
    const float* x   = (const float*)d_in[0];
    const float* w1  = (const float*)d_in[1];
    const float* b1  = (const float*)d_in[2];
    const float* w2  = (const float*)d_in[3];
    const float* b2  = (const float*)d_in[4];
    const float* W   = (const float*)d_in[5];
    float* out = (float*)d_out;

    cudaFuncSetAttribute(k_conv1,
                         cudaFuncAttributeMaxDynamicSharedMemorySize, 72512);
    cudaFuncSetAttribute(k_conv2mma,
                         cudaFuncAttributeMaxDynamicSharedMemorySize, 131072);

    k_conv1<<<dim3(512, 8), 256, 72512>>>(x, w1, b1);
    k_wprep<<<256, 256>>>(w2);
    k_conv2mma<<<dim3(72, 2), 512, 131072>>>(b2);
    k_squash_pc<<<2304, 256>>>();
    k_uhat<<<dim3(288, 8), 256>>>(W);

    k_route<<<dim3(512, 9), 160>>>(1);       // iter 0: uniform c
    k_squash_v<<<20, 256>>>(nullptr, 0);     // vsum = v0
    k_route<<<dim3(512, 9), 160>>>(0);       // iter 1
    k_squash_v<<<20, 256>>>(nullptr, 1);     // vsum += v1
    k_route<<<dim3(512, 9), 160>>>(0);       // iter 2
    k_squash_v<<<20, 256>>>(out, 2);         // out = v2
}